// round 8
// baseline (speedup 1.0000x reference)
#include <cuda_runtime.h>
#include <cuda_bf16.h>
#include <cstdint>

#define NN   882
#define TN   1764
#define MOCC 1024
#define BB   8
#define TT   6
#define KK   24
#define MAXD 32
#define CMAXD 24
#define PADCD 16
#define NW   56                      // ceil(1764/32)
#define DUMMY_EDGE (MOCC * MAXD)     // points at always-zero padding row of d_C

#define NBLK   120
#define NTHR   256
#define NT     (NBLK * NTHR)         // 30720 threads
#define NWARPS (NBLK * 8)            // 960 warps

#define MASK_WORDS (TT * MOCC * NW)  // 344064
#define CN_TASKS   (BB * MOCC)       // 8192
#define LT_TASKS   (BB * 2 * KK)     // 384 loss-term warp tasks
#define VN_TASKS   (BB * NW)         // 448 vn warp tasks (56 word-groups x 8 b)

// ---------------- device scratch (no allocations allowed) ----------------
__device__ int   d_row_deg[MOCC];
__device__ int   d_row_cols[MOCC][MAXD];
__device__ int   d_col_cnt[TN];               // atomic counters (self-resetting)
__device__ int   d_col_deg[TN];
__device__ int   d_col_edges[TN][CMAXD];      // edge idx = m*MAXD + slot (sorted, padded)
__device__ float d_C[BB][MOCC + 1][MAXD];     // c2v messages; row MOCC = permanent zeros
__device__ float d_wedge[TT][MOCC][MAXD];     // pre-gathered w_vn on edges
__device__ float d_Gamma[BB][TN];
__device__ float d_pm[BB][TN];                // masked prob for loss
__device__ float d_synsign[BB][MOCC];         // (1 - 2*syn)
__device__ float d_loss[BB][TT];
__device__ float d_lossterm[BB][2 * KK];
__device__ unsigned d_wneg[TT][MOCC][NW];     // sign bitmasks of w_vn[0..5]
__device__ unsigned d_wnz [TT][MOCC][NW];
__device__ unsigned d_gneg[BB][NW];           // sign bitmasks of Gamma
__device__ unsigned d_gnz [BB][NW];

// grid barrier state
__device__ volatile unsigned g_gen;
__device__ unsigned g_cnt;

__device__ __forceinline__ void gbar() {
    __syncthreads();
    if (threadIdx.x == 0) {
        __threadfence();
        unsigned gen = g_gen;
        unsigned prev = atomicAdd(&g_cnt, 1u);
        if (prev == (unsigned)(NBLK - 1)) {
            g_cnt = 0;
            __threadfence();
            g_gen = gen + 1;
        } else {
            while (g_gen == gen) {
                asm volatile("nanosleep.u32 64;");
            }
        }
        __threadfence();
    }
    __syncthreads();
}

// ---------------- accurate fp32 math (flag-independent; rn division) ----
__device__ __forceinline__ float acc_expf(float x) {
    if (x < -87.0f) return 0.0f;
    if (x >  88.0f) return __int_as_float(0x7f800000);
    float kf = rintf(x * 1.4426950408889634f);
    float r  = fmaf(-kf, 0.693359375f, x);
    r = fmaf(kf, 2.12194440e-4f, r);
    float p = 1.9841270e-4f;
    p = fmaf(r, p, 1.3888889e-3f);
    p = fmaf(r, p, 8.3333333e-3f);
    p = fmaf(r, p, 4.1666667e-2f);
    p = fmaf(r, p, 1.6666667e-1f);
    p = fmaf(r, p, 0.5f);
    p = fmaf(r, p, 1.0f);
    p = fmaf(r, p, 1.0f);
    int k = (int)kf;
    float sc = __int_as_float((k + 127) << 23);
    return p * sc;
}

// log for t>0; returns EXACT +-0.0f at t==1.0f (load-bearing for phi semantics)
__device__ __forceinline__ float acc_logf(float t) {
    int ix = __float_as_int(t);
    int e  = ((ix >> 23) & 0xff) - 127;
    float m = __int_as_float((ix & 0x007fffff) | 0x3f800000);   // [1,2)
    if (m > 1.4142135f) { m *= 0.5f; e += 1; }
    float f  = m - 1.0f;
    float s  = __fdiv_rn(f, 2.0f + f);
    float s2 = s * s;
    float p  = fmaf(s2, 0.11111111f, 0.14285714f);
    p = fmaf(s2, p, 0.2f);
    p = fmaf(s2, p, 0.33333333f);
    float lm = fmaf(2.0f * s, s2 * p, 2.0f * s);
    float r  = fmaf((float)e, 0.693359375f, lm);
    r = fmaf((float)e, -2.12194440e-4f, r);
    return r;
}

// XLA / Eigen fast-tanh (f32, FMA variant) — bit-matches jnp.tanh on GPU.
__device__ __forceinline__ float xla_tanhf(float x) {
    float ax = fabsf(x);
    float xc = fminf(fmaxf(x, -7.99881172180175781f), 7.99881172180175781f);
    float x2 = xc * xc;
    float p = -2.76076847742355e-16f;
    p = fmaf(x2, p,  2.00018790482477e-13f);
    p = fmaf(x2, p, -8.60467152213735e-11f);
    p = fmaf(x2, p,  5.12229709037114e-08f);
    p = fmaf(x2, p,  1.48572235717979e-05f);
    p = fmaf(x2, p,  6.37261928875436e-04f);
    p = fmaf(x2, p,  4.89352455891786e-03f);
    float num = xc * p;
    float q = 1.19825839466702e-06f;
    q = fmaf(x2, q, 1.18534705686654e-04f);
    q = fmaf(x2, q, 2.26843463243900e-03f);
    q = fmaf(x2, q, 4.89352518554385e-03f);
    float r = __fdiv_rn(num, q);
    return (ax < 0.0004f) ? x : r;
}

// phi(x) = -log(tanh(x/2)) with the reference's exact tanh quantization.
__device__ __forceinline__ float phi_f(float x) {
    return -acc_logf(xla_tanhf(0.5f * x));
}

// |sin(argf)| accurate to ~1e-12: dd-pi reduction + odd Taylor to r^15.
__device__ __forceinline__ float abs_sin_acc(float argf) {
    double a = (double)argf;
    double k = rint(a * 0.31830988618379067154);
    double r = fma(-k, 3.141592653589793116, a);
    r = fma(-k, 1.2246467991473531772e-16, r);
    double r2 = r * r;
    double p = -7.6471637318198164759e-13;
    p = fma(r2, p,  1.6059043836821614599e-10);
    p = fma(r2, p, -2.5052108385441718775e-08);
    p = fma(r2, p,  2.7557319223985890653e-06);
    p = fma(r2, p, -1.9841269841269841253e-04);
    p = fma(r2, p,  8.3333333333333332177e-03);
    p = fma(r2, p, -1.6666666666666666574e-01);
    p = fma(r2, p,  1.0);
    return fabsf((float)(r * p));
}

// ---------------- the one kernel ----------------
__global__ void __launch_bounds__(NTHR, 1)
k_all(const float* __restrict__ ex, const float* __restrict__ ez,
      const float* __restrict__ ep, const float* __restrict__ H,
      const float* __restrict__ Gx, const float* __restrict__ Gz,
      const float* __restrict__ w_vn, const float* __restrict__ w_llr,
      const float* __restrict__ w_cn, float* __restrict__ out)
{
    const int tid  = threadIdx.x;
    const int gtid = blockIdx.x * NTHR + tid;
    const int lane = tid & 31;
    const int gwid = gtid >> 5;

    // ---- phase 0: row adjacency + syndromes + C zero; w_vn sign masks ----
    for (int m = gwid; m < MOCC; m += NWARPS) {
        int deg = 0;
        for (int c = 0; c < NW; c++) {
            int j = c * 32 + lane;
            float h = (j < TN) ? H[(size_t)m * TN + j] : 0.0f;
            unsigned bal = __ballot_sync(0xffffffffu, h != 0.0f);
            if (h != 0.0f) {
                int pos = deg + __popc(bal & ((1u << lane) - 1u));
                if (pos < MAXD) d_row_cols[m][pos] = j;
            }
            deg += __popc(bal);
        }
        if (deg > MAXD) deg = MAXD;
        if (lane == 0) d_row_deg[m] = deg;
        for (int b = 0; b < BB; b++) d_C[b][m][lane] = 0.0f;
        __syncwarp();
        bool act = (lane < deg);
        int col = act ? d_row_cols[m][lane] : 0;
        if (act) {
            int pos = atomicAdd(&d_col_cnt[col], 1);
            if (pos < CMAXD) d_col_edges[col][pos] = m * MAXD + lane;
        }
        for (int b = 0; b < BB; b++) {
            float e = 0.0f;
            if (act) e = (col < NN) ? ex[b * NN + col] : ez[b * NN + (col - NN)];
            unsigned bal = __ballot_sync(0xffffffffu, act && (e != 0.0f));
            if (lane == 0) d_synsign[b][m] = (__popc(bal) & 1) ? -1.0f : 1.0f;
        }
    }
    for (int t = gtid; t < MASK_WORDS; t += NT) {
        int row = t / NW, c = t % NW;
        const float* base = w_vn + (size_t)row * TN + c * 32;
        int nvec = (c == NW - 1) ? 1 : 8;             // last word: only 4 floats
        unsigned neg = 0, nz = 0;
        for (int v = 0; v < nvec; v++) {
            float4 f = reinterpret_cast<const float4*>(base)[v];
            int k = v * 4;
            neg |= ((f.x < 0.0f) ? 1u : 0u) << k;
            neg |= ((f.y < 0.0f) ? 1u : 0u) << (k + 1);
            neg |= ((f.z < 0.0f) ? 1u : 0u) << (k + 2);
            neg |= ((f.w < 0.0f) ? 1u : 0u) << (k + 3);
            nz  |= ((f.x != 0.0f) ? 1u : 0u) << k;
            nz  |= ((f.y != 0.0f) ? 1u : 0u) << (k + 1);
            nz  |= ((f.z != 0.0f) ? 1u : 0u) << (k + 2);
            nz  |= ((f.w != 0.0f) ? 1u : 0u) << (k + 3);
        }
        (&d_wneg[0][0][0])[(size_t)row * NW + c] = neg;
        (&d_wnz [0][0][0])[(size_t)row * NW + c] = nz;
    }
    gbar();

    // ---- phase 1: wedge gather + column sort/pad ----
    for (int t = gtid; t < TT * MOCC * MAXD; t += NT) {
        int slot = t & (MAXD - 1);
        int m    = (t >> 5) & (MOCC - 1);
        int it   = t >> 15;
        float w = 0.0f;
        if (slot < d_row_deg[m]) {
            int col = d_row_cols[m][slot];
            w = w_vn[((size_t)it * MOCC + m) * TN + col];
        }
        d_wedge[it][m][slot] = w;
    }
    for (int j = gtid; j < TN; j += NT) {
        int cnt = d_col_cnt[j];
        if (cnt > CMAXD) cnt = CMAXD;
        int e[CMAXD];
        for (int k = 0; k < cnt; k++) e[k] = d_col_edges[j][k];
        for (int i = 1; i < cnt; i++) {               // ascending m order
            int key = e[i], p = i - 1;
            while (p >= 0 && e[p] > key) { e[p + 1] = e[p]; p--; }
            e[p + 1] = key;
        }
        for (int k = 0; k < cnt; k++) d_col_edges[j][k] = e[k];
        for (int k = cnt; k < PADCD; k++) d_col_edges[j][k] = DUMMY_EDGE;
        d_col_deg[j] = cnt;
        d_col_cnt[j] = 0;                             // reset for next replay
    }
    gbar();

    float e0  = ep[0];
    float llr = acc_logf(__fdiv_rn(1.0f - e0, e0));

    for (int it = 0; it < TT; it++) {
        // ---- CN phase (+ loss terms for it-1) ----
        float gconst = llr * w_llr[0];                // used only when it==0
        for (int t = gwid; t < CN_TASKS + LT_TASKS; t += NWARPS) {
            if (t < CN_TASKS) {
                int b = t >> 10, m = t & 1023;
                const unsigned* wneg = d_wneg[it][m];
                const unsigned* wnz  = d_wnz [it][m];
                int cnt = 0;
                if (it == 0) {
                    unsigned GN = (gconst < 0.0f) ? 0xffffffffu : 0u;
                    unsigned GZ = (gconst != 0.0f) ? 0xffffffffu : 0u;
                    for (int c = lane; c < NW; c += 32)
                        cnt += __popc((GN ^ wneg[c]) & GZ & wnz[c]);
                } else {
                    const unsigned* gneg = d_gneg[b];
                    const unsigned* gnz  = d_gnz [b];
                    for (int c = lane; c < NW; c += 32)
                        cnt += __popc((gneg[c] ^ wneg[c]) & gnz[c] & wnz[c]);
                }
                for (int o = 16; o; o >>= 1) cnt += __shfl_xor_sync(0xffffffffu, cnt, o);
                int parity = cnt & 1;

                int deg = d_row_deg[m];
                bool act = (lane < deg);
                float V = 0.0f, phi = 0.0f;
                int corr = 0;
                if (act) {
                    int j = d_row_cols[m][lane];
                    float G = (it == 0) ? gconst : d_Gamma[b][j];
                    float Cold = d_C[b][m][lane];
                    float w = d_wedge[it][m][lane];
                    float x = G - Cold;
                    x = fminf(fmaxf(x, -30.0f), 30.0f);
                    V = x * w;
                    int pneg = (((G < 0.0f) != (w < 0.0f)) && (G != 0.0f) && (w != 0.0f)) ? 1 : 0;
                    int vneg = (V < 0.0f) ? 1 : 0;
                    corr = pneg ^ vneg;
                    if (V != 0.0f) phi = phi_f(fabsf(V));
                }
                unsigned cb = __ballot_sync(0xffffffffu, corr);
                parity ^= (__popc(cb) & 1);

                float A = phi;
                for (int o = 16; o; o >>= 1) A += __shfl_xor_sync(0xffffffffu, A, o);

                if (act) {
                    float P = parity ? -1.0f : 1.0f;
                    float first = (V < 0.0f) ? -P : P;
                    float s2 = A - phi;
                    float second = (s2 != 0.0f) ? phi_f(s2) : 0.0f;
                    d_C[b][m][lane] = ((first * second) * d_synsign[b][m]) * w_cn[it * MOCC + m];
                }
            } else if (it > 0) {
                int idx = t - CN_TASKS;
                int b = idx / (2 * KK), k2 = idx % (2 * KK);
                const float* Grow  = (k2 < KK) ? Gx + (size_t)k2 * NN : Gz + (size_t)(k2 - KK) * NN;
                const float* pmrow = (k2 < KK) ? &d_pm[b][0] : &d_pm[b][NN];
                float s = 0.0f;
                for (int n = lane; n < NN; n += 32) s += pmrow[n] * Grow[n];
                for (int o = 16; o; o >>= 1) s += __shfl_xor_sync(0xffffffffu, s, o);
                if (lane == 0) d_lossterm[b][k2] = abs_sin_acc(1.5707964f * s);
            }
        }
        gbar();

        // ---- VN phase (+ fixed-order loss sum for it-1) ----
        float wl = w_llr[it + 1];
        for (int t = gwid; t < VN_TASKS + BB; t += NWARPS) {
            if (t < VN_TASKS) {
                int b = t / NW, jw = t % NW;
                int j = jw * 32 + lane;
                bool in = (j < TN);
                float g = 0.0f;
                if (in) {
                    const float* Cb = &d_C[b][0][0];
                    float sum = 0.0f;
                    #pragma unroll
                    for (int k = 0; k < PADCD; k++) sum += Cb[d_col_edges[j][k]];
                    int cd = d_col_deg[j];
                    if (cd > PADCD)
                        for (int k = PADCD; k < cd; k++) sum += Cb[d_col_edges[j][k]];
                    g = llr * wl + sum;
                    d_Gamma[b][j] = g;
                    float mask = (j < NN) ? ex[b * NN + j] : ez[b * NN + (j - NN)];
                    float pmv = 0.0f;
                    if (mask == 1.0f) pmv = __fdiv_rn(1.0f, 1.0f + acc_expf(g));
                    d_pm[b][j] = pmv;
                }
                unsigned bneg = __ballot_sync(0xffffffffu, in && (g < 0.0f));
                unsigned bnz  = __ballot_sync(0xffffffffu, in && (g != 0.0f));
                if (lane == 0) { d_gneg[b][jw] = bneg; d_gnz[b][jw] = bnz; }
            } else if (it > 0 && lane == 0) {
                int b = t - VN_TASKS;
                float tsum = 0.0f;
                for (int k = 0; k < 2 * KK; k++) tsum += d_lossterm[b][k];
                d_loss[b][it - 1] = tsum;
            }
        }
        gbar();
    }

    // ---- epilogue: loss terms for it = TT-1 ----
    for (int t = gwid; t < LT_TASKS; t += NWARPS) {
        int b = t / (2 * KK), k2 = t % (2 * KK);
        const float* Grow  = (k2 < KK) ? Gx + (size_t)k2 * NN : Gz + (size_t)(k2 - KK) * NN;
        const float* pmrow = (k2 < KK) ? &d_pm[b][0] : &d_pm[b][NN];
        float s = 0.0f;
        for (int n = lane; n < NN; n += 32) s += pmrow[n] * Grow[n];
        for (int o = 16; o; o >>= 1) s += __shfl_xor_sync(0xffffffffu, s, o);
        if (lane == 0) d_lossterm[b][k2] = abs_sin_acc(1.5707964f * s);
    }
    gbar();

    // ---- final reduction (block 0, warp 0) ----
    if (blockIdx.x == 0 && tid < 32) {
        float per_b = 0.0f;
        if (lane < BB) {
            float v[TT];
            for (int i = 0; i < TT - 1; i++) v[i] = d_loss[lane][i];
            float s5 = 0.0f;
            for (int k = 0; k < 2 * KK; k++) s5 += d_lossterm[lane][k];
            v[TT - 1] = s5;
            float best = v[0]; int bi = 0;
            for (int i = 1; i < TT; i++) if (v[i] < best) { best = v[i]; bi = i; }
            float cs = 0.0f;
            for (int i = 0; i <= bi; i++) cs += v[i];
            per_b = __fdiv_rn(cs, (float)(bi + 1));
        }
        float tot = 0.0f;
        for (int b = 0; b < BB; b++) tot += __shfl_sync(0xffffffffu, per_b, b);
        if (lane == 0) out[0] = tot * 0.125f;
    }
}

// ---------------- launch ----------------
extern "C" void kernel_launch(void* const* d_in, const int* in_sizes, int n_in,
                              void* d_out, int out_size) {
    const float* ex    = (const float*)d_in[0];
    const float* ez    = (const float*)d_in[1];
    const float* ep    = (const float*)d_in[2];
    const float* H     = (const float*)d_in[3];
    const float* Gx    = (const float*)d_in[6];
    const float* Gz    = (const float*)d_in[7];
    const float* w_vn  = (const float*)d_in[8];
    const float* w_llr = (const float*)d_in[9];
    const float* w_cn  = (const float*)d_in[10];
    float* out = (float*)d_out;

    k_all<<<NBLK, NTHR>>>(ex, ez, ep, H, Gx, Gz, w_vn, w_llr, w_cn, out);
}

// round 9
// speedup vs baseline: 1.1724x; 1.1724x over previous
#include <cuda_runtime.h>
#include <cuda_bf16.h>
#include <cstdint>

#define NN   882
#define TN   1764
#define MOCC 1024
#define BB   8
#define TT   6
#define KK   24
#define MAXD 32
#define CMAXD 24
#define PADCD 16
#define NW   56                      // ceil(1764/32)
#define DUMMY_EDGE (MOCC * MAXD)     // points at always-zero padding row of d_C

// persistent iteration kernel geometry
#define NBLK   120
#define NTHR   256
#define NWARPS (NBLK * 8)            // 960 warps

#define MASK_WORDS (TT * MOCC * NW)  // 344064
#define MASK_BLOCKS ((MASK_WORDS + 255) / 256)       // 1344
#define GATH_BLOCKS (TT * MOCC * MAXD / 256)         // 768
#define SORT_BLOCKS ((TN + 255) / 256)               // 7
#define CN_TASKS   (BB * MOCC)       // 8192
#define LT_TASKS   (BB * 2 * KK)     // 384 loss-term warp tasks
#define VN_TASKS   (BB * NW)         // 448 vn warp tasks

// ---------------- device scratch (no allocations allowed) ----------------
__device__ int   d_row_deg[MOCC];
__device__ int   d_row_cols[MOCC][MAXD];
__device__ int   d_col_cnt[TN];               // atomic counters (self-resetting)
__device__ int   d_col_deg[TN];
__device__ int   d_col_edges[TN][CMAXD];      // edge idx = m*MAXD + slot (sorted, padded)
__device__ float d_C[BB][MOCC + 1][MAXD];     // c2v messages; row MOCC = permanent zeros
__device__ float d_wedge[TT][MOCC][MAXD];     // pre-gathered w_vn on edges
__device__ float d_Gamma[BB][TN];
__device__ float d_pm[BB][TN];                // masked prob for loss
__device__ float d_synsign[BB][MOCC];         // (1 - 2*syn)
__device__ float d_loss[BB][TT];
__device__ float d_lossterm[BB][2 * KK];
__device__ unsigned d_wneg[TT][MOCC][NW];     // sign bitmasks of w_vn[0..5]
__device__ unsigned d_wnz [TT][MOCC][NW];
__device__ unsigned d_gneg[BB][NW];           // sign bitmasks of Gamma
__device__ unsigned d_gnz [BB][NW];

// grid barrier state
__device__ volatile unsigned g_gen;
__device__ unsigned g_cnt;

__device__ __forceinline__ void gbar() {
    __syncthreads();
    if (threadIdx.x == 0) {
        __threadfence();
        unsigned gen = g_gen;
        unsigned prev = atomicAdd(&g_cnt, 1u);
        if (prev == (unsigned)(NBLK - 1)) {
            g_cnt = 0;
            __threadfence();
            g_gen = gen + 1;
        } else {
            while (g_gen == gen) {
                asm volatile("nanosleep.u32 32;");
            }
        }
        __threadfence();
    }
    __syncthreads();
}

// ---------------- accurate fp32 math (flag-independent; rn division) ----
__device__ __forceinline__ float acc_expf(float x) {
    if (x < -87.0f) return 0.0f;
    if (x >  88.0f) return __int_as_float(0x7f800000);
    float kf = rintf(x * 1.4426950408889634f);
    float r  = fmaf(-kf, 0.693359375f, x);
    r = fmaf(kf, 2.12194440e-4f, r);
    float p = 1.9841270e-4f;
    p = fmaf(r, p, 1.3888889e-3f);
    p = fmaf(r, p, 8.3333333e-3f);
    p = fmaf(r, p, 4.1666667e-2f);
    p = fmaf(r, p, 1.6666667e-1f);
    p = fmaf(r, p, 0.5f);
    p = fmaf(r, p, 1.0f);
    p = fmaf(r, p, 1.0f);
    int k = (int)kf;
    float sc = __int_as_float((k + 127) << 23);
    return p * sc;
}

// log for t>0; returns EXACT +-0.0f at t==1.0f (load-bearing for phi semantics)
__device__ __forceinline__ float acc_logf(float t) {
    int ix = __float_as_int(t);
    int e  = ((ix >> 23) & 0xff) - 127;
    float m = __int_as_float((ix & 0x007fffff) | 0x3f800000);   // [1,2)
    if (m > 1.4142135f) { m *= 0.5f; e += 1; }
    float f  = m - 1.0f;
    float s  = __fdiv_rn(f, 2.0f + f);
    float s2 = s * s;
    float p  = fmaf(s2, 0.11111111f, 0.14285714f);
    p = fmaf(s2, p, 0.2f);
    p = fmaf(s2, p, 0.33333333f);
    float lm = fmaf(2.0f * s, s2 * p, 2.0f * s);
    float r  = fmaf((float)e, 0.693359375f, lm);
    r = fmaf((float)e, -2.12194440e-4f, r);
    return r;
}

// XLA / Eigen fast-tanh (f32, FMA variant) — bit-matches jnp.tanh on GPU.
__device__ __forceinline__ float xla_tanhf(float x) {
    float ax = fabsf(x);
    float xc = fminf(fmaxf(x, -7.99881172180175781f), 7.99881172180175781f);
    float x2 = xc * xc;
    float p = -2.76076847742355e-16f;
    p = fmaf(x2, p,  2.00018790482477e-13f);
    p = fmaf(x2, p, -8.60467152213735e-11f);
    p = fmaf(x2, p,  5.12229709037114e-08f);
    p = fmaf(x2, p,  1.48572235717979e-05f);
    p = fmaf(x2, p,  6.37261928875436e-04f);
    p = fmaf(x2, p,  4.89352455891786e-03f);
    float num = xc * p;
    float q = 1.19825839466702e-06f;
    q = fmaf(x2, q, 1.18534705686654e-04f);
    q = fmaf(x2, q, 2.26843463243900e-03f);
    q = fmaf(x2, q, 4.89352518554385e-03f);
    float r = __fdiv_rn(num, q);
    return (ax < 0.0004f) ? x : r;
}

// phi(x) = -log(tanh(x/2)) with the reference's exact tanh quantization.
__device__ __forceinline__ float phi_f(float x) {
    return -acc_logf(xla_tanhf(0.5f * x));
}

// |sin(argf)| accurate to ~1e-12: dd-pi reduction + odd Taylor to r^15.
__device__ __forceinline__ float abs_sin_acc(float argf) {
    double a = (double)argf;
    double k = rint(a * 0.31830988618379067154);
    double r = fma(-k, 3.141592653589793116, a);
    r = fma(-k, 1.2246467991473531772e-16, r);
    double r2 = r * r;
    double p = -7.6471637318198164759e-13;
    p = fma(r2, p,  1.6059043836821614599e-10);
    p = fma(r2, p, -2.5052108385441718775e-08);
    p = fma(r2, p,  2.7557319223985890653e-06);
    p = fma(r2, p, -1.9841269841269841253e-04);
    p = fma(r2, p,  8.3333333333333332177e-03);
    p = fma(r2, p, -1.6666666666666666574e-01);
    p = fma(r2, p,  1.0);
    return fabsf((float)(r * p));
}

// ---------------- wide preprocessing kernels ----------------
// Build row adjacency, zero c2v, syndrome parities, atomic column build.
__global__ void k_rows(const float* __restrict__ H,
                       const float* __restrict__ ex, const float* __restrict__ ez) {
    int gw = (blockIdx.x * blockDim.x + threadIdx.x) >> 5;
    int lane = threadIdx.x & 31;
    if (gw >= MOCC) return;
    int m = gw, deg = 0;
    for (int c = 0; c < NW; c++) {
        int j = c * 32 + lane;
        float h = (j < TN) ? H[(size_t)m * TN + j] : 0.0f;
        unsigned bal = __ballot_sync(0xffffffffu, h != 0.0f);
        if (h != 0.0f) {
            int pos = deg + __popc(bal & ((1u << lane) - 1u));
            if (pos < MAXD) d_row_cols[m][pos] = j;
        }
        deg += __popc(bal);
    }
    if (deg > MAXD) deg = MAXD;
    if (lane == 0) d_row_deg[m] = deg;
    for (int b = 0; b < BB; b++) d_C[b][m][lane] = 0.0f;
    __syncwarp();
    bool act = (lane < deg);
    int col = act ? d_row_cols[m][lane] : 0;
    if (act) {
        int pos = atomicAdd(&d_col_cnt[col], 1);
        if (pos < CMAXD) d_col_edges[col][pos] = m * MAXD + lane;
    }
    for (int b = 0; b < BB; b++) {
        float e = 0.0f;
        if (act) e = (col < NN) ? ex[b * NN + col] : ez[b * NN + (col - NN)];
        unsigned bal = __ballot_sync(0xffffffffu, act && (e != 0.0f));
        if (lane == 0) d_synsign[b][m] = (__popc(bal) & 1) ? -1.0f : 1.0f;
    }
}

// Phase A: thread-per-mask-word float4 scans; B: edge gather; C: col sort/pad.
__global__ void k_wprep(const float* __restrict__ w_vn) {
    if (blockIdx.x < MASK_BLOCKS) {
        int t = blockIdx.x * 256 + threadIdx.x;
        if (t >= MASK_WORDS) return;
        int row = t / NW, c = t % NW;
        const float* base = w_vn + (size_t)row * TN + c * 32;
        int nvec = (c == NW - 1) ? 1 : 8;            // last word: only 4 floats
        unsigned neg = 0, nz = 0;
        for (int v = 0; v < nvec; v++) {
            float4 f = reinterpret_cast<const float4*>(base)[v];
            int k = v * 4;
            neg |= ((f.x < 0.0f) ? 1u : 0u) << k;
            neg |= ((f.y < 0.0f) ? 1u : 0u) << (k + 1);
            neg |= ((f.z < 0.0f) ? 1u : 0u) << (k + 2);
            neg |= ((f.w < 0.0f) ? 1u : 0u) << (k + 3);
            nz  |= ((f.x != 0.0f) ? 1u : 0u) << k;
            nz  |= ((f.y != 0.0f) ? 1u : 0u) << (k + 1);
            nz  |= ((f.z != 0.0f) ? 1u : 0u) << (k + 2);
            nz  |= ((f.w != 0.0f) ? 1u : 0u) << (k + 3);
        }
        (&d_wneg[0][0][0])[(size_t)row * NW + c] = neg;
        (&d_wnz [0][0][0])[(size_t)row * NW + c] = nz;
    } else if (blockIdx.x < MASK_BLOCKS + GATH_BLOCKS) {
        int t = (blockIdx.x - MASK_BLOCKS) * 256 + threadIdx.x;
        int slot = t & (MAXD - 1);
        int m    = (t >> 5) & (MOCC - 1);
        int it   = t >> 15;
        float w = 0.0f;
        if (slot < d_row_deg[m]) {
            int col = d_row_cols[m][slot];
            w = w_vn[((size_t)it * MOCC + m) * TN + col];
        }
        d_wedge[it][m][slot] = w;
    } else {
        int j = (blockIdx.x - MASK_BLOCKS - GATH_BLOCKS) * 256 + threadIdx.x;
        if (j >= TN) return;
        int cnt = d_col_cnt[j];
        if (cnt > CMAXD) cnt = CMAXD;
        int e[CMAXD];
        for (int k = 0; k < cnt; k++) e[k] = d_col_edges[j][k];
        for (int i = 1; i < cnt; i++) {               // ascending m order
            int key = e[i], p = i - 1;
            while (p >= 0 && e[p] > key) { e[p + 1] = e[p]; p--; }
            e[p + 1] = key;
        }
        for (int k = 0; k < cnt; k++) d_col_edges[j][k] = e[k];
        for (int k = cnt; k < PADCD; k++) d_col_edges[j][k] = DUMMY_EDGE;
        d_col_deg[j] = cnt;
        d_col_cnt[j] = 0;                             // reset for next replay
    }
}

// ---------------- persistent iteration kernel ----------------
__global__ void __launch_bounds__(NTHR)
k_iter(const float* __restrict__ ex, const float* __restrict__ ez,
       const float* __restrict__ ep,
       const float* __restrict__ Gx, const float* __restrict__ Gz,
       const float* __restrict__ w_llr, const float* __restrict__ w_cn,
       float* __restrict__ out)
{
    const int tid  = threadIdx.x;
    const int gtid = blockIdx.x * NTHR + tid;
    const int lane = tid & 31;
    const int gwid = gtid >> 5;

    float e0  = ep[0];
    float llr = acc_logf(__fdiv_rn(1.0f - e0, e0));

    for (int it = 0; it < TT; it++) {
        // ---- CN phase (+ loss terms for it-1) ----
        float gconst = llr * w_llr[0];                // used only when it==0
        for (int t = gwid; t < CN_TASKS + LT_TASKS; t += NWARPS) {
            if (t < CN_TASKS) {
                int b = t >> 10, m = t & 1023;
                const unsigned* wneg = d_wneg[it][m];
                const unsigned* wnz  = d_wnz [it][m];
                int cnt = 0;
                if (it == 0) {
                    unsigned GN = (gconst < 0.0f) ? 0xffffffffu : 0u;
                    unsigned GZ = (gconst != 0.0f) ? 0xffffffffu : 0u;
                    for (int c = lane; c < NW; c += 32)
                        cnt += __popc((GN ^ wneg[c]) & GZ & wnz[c]);
                } else {
                    const unsigned* gneg = d_gneg[b];
                    const unsigned* gnz  = d_gnz [b];
                    for (int c = lane; c < NW; c += 32)
                        cnt += __popc((gneg[c] ^ wneg[c]) & gnz[c] & wnz[c]);
                }
                for (int o = 16; o; o >>= 1) cnt += __shfl_xor_sync(0xffffffffu, cnt, o);
                int parity = cnt & 1;

                int deg = d_row_deg[m];
                bool act = (lane < deg);
                float V = 0.0f, phi = 0.0f;
                int corr = 0;
                if (act) {
                    int j = d_row_cols[m][lane];
                    float G = (it == 0) ? gconst : d_Gamma[b][j];
                    float Cold = d_C[b][m][lane];
                    float w = d_wedge[it][m][lane];
                    float x = G - Cold;
                    x = fminf(fmaxf(x, -30.0f), 30.0f);
                    V = x * w;
                    int pneg = (((G < 0.0f) != (w < 0.0f)) && (G != 0.0f) && (w != 0.0f)) ? 1 : 0;
                    int vneg = (V < 0.0f) ? 1 : 0;
                    corr = pneg ^ vneg;
                    if (V != 0.0f) phi = phi_f(fabsf(V));
                }
                unsigned cb = __ballot_sync(0xffffffffu, corr);
                parity ^= (__popc(cb) & 1);

                float A = phi;
                for (int o = 16; o; o >>= 1) A += __shfl_xor_sync(0xffffffffu, A, o);

                if (act) {
                    float P = parity ? -1.0f : 1.0f;
                    float first = (V < 0.0f) ? -P : P;
                    float s2 = A - phi;
                    float second = (s2 != 0.0f) ? phi_f(s2) : 0.0f;
                    d_C[b][m][lane] = ((first * second) * d_synsign[b][m]) * w_cn[it * MOCC + m];
                }
            } else if (it > 0) {
                int idx = t - CN_TASKS;
                int b = idx / (2 * KK), k2 = idx % (2 * KK);
                const float* Grow  = (k2 < KK) ? Gx + (size_t)k2 * NN : Gz + (size_t)(k2 - KK) * NN;
                const float* pmrow = (k2 < KK) ? &d_pm[b][0] : &d_pm[b][NN];
                float s = 0.0f;
                for (int n = lane; n < NN; n += 32) s += pmrow[n] * Grow[n];
                for (int o = 16; o; o >>= 1) s += __shfl_xor_sync(0xffffffffu, s, o);
                if (lane == 0) d_lossterm[b][k2] = abs_sin_acc(1.5707964f * s);
            }
        }
        gbar();

        // ---- VN phase (+ fixed-order loss sum for it-1) ----
        float wl = w_llr[it + 1];
        for (int t = gwid; t < VN_TASKS + BB; t += NWARPS) {
            if (t < VN_TASKS) {
                int b = t / NW, jw = t % NW;
                int j = jw * 32 + lane;
                bool in = (j < TN);
                float g = 0.0f;
                if (in) {
                    const float* Cb = &d_C[b][0][0];
                    float sum = 0.0f;
                    #pragma unroll
                    for (int k = 0; k < PADCD; k++) sum += Cb[d_col_edges[j][k]];
                    int cd = d_col_deg[j];
                    if (cd > PADCD)
                        for (int k = PADCD; k < cd; k++) sum += Cb[d_col_edges[j][k]];
                    g = llr * wl + sum;
                    d_Gamma[b][j] = g;
                    float mask = (j < NN) ? ex[b * NN + j] : ez[b * NN + (j - NN)];
                    float pmv = 0.0f;
                    if (mask == 1.0f) pmv = __fdiv_rn(1.0f, 1.0f + acc_expf(g));
                    d_pm[b][j] = pmv;
                }
                unsigned bneg = __ballot_sync(0xffffffffu, in && (g < 0.0f));
                unsigned bnz  = __ballot_sync(0xffffffffu, in && (g != 0.0f));
                if (lane == 0) { d_gneg[b][jw] = bneg; d_gnz[b][jw] = bnz; }
            } else if (it > 0 && lane == 0) {
                int b = t - VN_TASKS;
                float tsum = 0.0f;
                for (int k = 0; k < 2 * KK; k++) tsum += d_lossterm[b][k];
                d_loss[b][it - 1] = tsum;
            }
        }
        gbar();
    }

    // ---- epilogue: loss terms for it = TT-1 ----
    for (int t = gwid; t < LT_TASKS; t += NWARPS) {
        int b = t / (2 * KK), k2 = t % (2 * KK);
        const float* Grow  = (k2 < KK) ? Gx + (size_t)k2 * NN : Gz + (size_t)(k2 - KK) * NN;
        const float* pmrow = (k2 < KK) ? &d_pm[b][0] : &d_pm[b][NN];
        float s = 0.0f;
        for (int n = lane; n < NN; n += 32) s += pmrow[n] * Grow[n];
        for (int o = 16; o; o >>= 1) s += __shfl_xor_sync(0xffffffffu, s, o);
        if (lane == 0) d_lossterm[b][k2] = abs_sin_acc(1.5707964f * s);
    }
    gbar();

    // ---- final reduction (block 0, warp 0) ----
    if (blockIdx.x == 0 && tid < 32) {
        float per_b = 0.0f;
        if (lane < BB) {
            float v[TT];
            for (int i = 0; i < TT - 1; i++) v[i] = d_loss[lane][i];
            float s5 = 0.0f;
            for (int k = 0; k < 2 * KK; k++) s5 += d_lossterm[lane][k];
            v[TT - 1] = s5;
            float best = v[0]; int bi = 0;
            for (int i = 1; i < TT; i++) if (v[i] < best) { best = v[i]; bi = i; }
            float cs = 0.0f;
            for (int i = 0; i <= bi; i++) cs += v[i];
            per_b = __fdiv_rn(cs, (float)(bi + 1));
        }
        float tot = 0.0f;
        for (int b = 0; b < BB; b++) tot += __shfl_sync(0xffffffffu, per_b, b);
        if (lane == 0) out[0] = tot * 0.125f;
    }
}

// ---------------- launch ----------------
extern "C" void kernel_launch(void* const* d_in, const int* in_sizes, int n_in,
                              void* d_out, int out_size) {
    const float* ex    = (const float*)d_in[0];
    const float* ez    = (const float*)d_in[1];
    const float* ep    = (const float*)d_in[2];
    const float* H     = (const float*)d_in[3];
    const float* Gx    = (const float*)d_in[6];
    const float* Gz    = (const float*)d_in[7];
    const float* w_vn  = (const float*)d_in[8];
    const float* w_llr = (const float*)d_in[9];
    const float* w_cn  = (const float*)d_in[10];
    float* out = (float*)d_out;

    k_rows <<<MOCC / 8, 256>>>(H, ex, ez);
    k_wprep<<<MASK_BLOCKS + GATH_BLOCKS + SORT_BLOCKS, 256>>>(w_vn);
    k_iter <<<NBLK, NTHR>>>(ex, ez, ep, Gx, Gz, w_llr, w_cn, out);
}

// round 10
// speedup vs baseline: 1.3997x; 1.1939x over previous
#include <cuda_runtime.h>
#include <cuda_bf16.h>
#include <cstdint>

#define NN   882
#define TN   1764
#define MOCC 1024
#define BB   8
#define TT   6
#define KK   24
#define MAXD 32
#define CMAXD 24
#define PADCD 16
#define NW   56                      // ceil(1764/32)
#define DUMMY_EDGE (MOCC * MAXD)     // points at always-zero padding row of d_C

// persistent kernel geometry: 120 blocks x 1024 threads, 1 block/SM
#define NBLK   120
#define NTHR   1024
#define NT     (NBLK * NTHR)         // 122880 threads
#define NWARPS (NBLK * 32)           // 3840 warps

#define HW_WORDS  (MOCC * NW)        // 57344
#define WW_WORDS  (TT * MOCC * NW)   // 344064
#define SCAN_WORDS (HW_WORDS + WW_WORDS)             // 401408 = 1568*256
#define CN_TASKS   (BB * MOCC)       // 8192
#define LT_TASKS   (BB * 2 * KK)     // 384 loss-term warp tasks
#define VN_TASKS   (BB * NW)         // 448 vn warp tasks

// ---------------- device scratch (no allocations allowed) ----------------
__device__ unsigned d_hmask[MOCC][NW];        // H nonzero bitmasks
__device__ int   d_row_deg[MOCC];
__device__ int   d_row_cols[MOCC][MAXD];
__device__ int   d_col_cnt[TN];               // atomic counters (self-resetting)
__device__ int   d_col_deg[TN];
__device__ int   d_col_edges[TN][CMAXD];      // edge idx = m*MAXD + slot (sorted, padded)
__device__ float d_C[BB][MOCC + 1][MAXD];     // c2v messages; row MOCC = permanent zeros
__device__ float d_wedge[TT][MOCC][MAXD];     // pre-gathered w_vn on edges
__device__ float d_Gamma[BB][TN];
__device__ float d_pm[BB][TN];                // masked prob for loss
__device__ float d_synsign[BB][MOCC];         // (1 - 2*syn)
__device__ float d_loss[BB][TT];
__device__ float d_lossterm[BB][2 * KK];
__device__ unsigned d_wneg[TT][MOCC][NW];     // sign bitmasks of w_vn[0..5]
__device__ unsigned d_wnz [TT][MOCC][NW];
__device__ unsigned d_gneg[BB][NW];           // sign bitmasks of Gamma
__device__ unsigned d_gnz [BB][NW];

// grid barrier state
__device__ volatile unsigned g_gen;
__device__ unsigned g_cnt;

__device__ __forceinline__ void gbar() {
    __syncthreads();
    if (threadIdx.x == 0) {
        __threadfence();
        unsigned gen = g_gen;
        unsigned prev = atomicAdd(&g_cnt, 1u);
        if (prev == (unsigned)(NBLK - 1)) {
            g_cnt = 0;
            __threadfence();
            g_gen = gen + 1;
        } else {
            while (g_gen == gen) {
                asm volatile("nanosleep.u32 32;");
            }
        }
        __threadfence();
    }
    __syncthreads();
}

// ---------------- accurate fp32 math (flag-independent; rn division) ----
__device__ __forceinline__ float acc_expf(float x) {
    if (x < -87.0f) return 0.0f;
    if (x >  88.0f) return __int_as_float(0x7f800000);
    float kf = rintf(x * 1.4426950408889634f);
    float r  = fmaf(-kf, 0.693359375f, x);
    r = fmaf(kf, 2.12194440e-4f, r);
    float p = 1.9841270e-4f;
    p = fmaf(r, p, 1.3888889e-3f);
    p = fmaf(r, p, 8.3333333e-3f);
    p = fmaf(r, p, 4.1666667e-2f);
    p = fmaf(r, p, 1.6666667e-1f);
    p = fmaf(r, p, 0.5f);
    p = fmaf(r, p, 1.0f);
    p = fmaf(r, p, 1.0f);
    int k = (int)kf;
    float sc = __int_as_float((k + 127) << 23);
    return p * sc;
}

// log for t>0; returns EXACT +-0.0f at t==1.0f (load-bearing for phi semantics)
__device__ __forceinline__ float acc_logf(float t) {
    int ix = __float_as_int(t);
    int e  = ((ix >> 23) & 0xff) - 127;
    float m = __int_as_float((ix & 0x007fffff) | 0x3f800000);   // [1,2)
    if (m > 1.4142135f) { m *= 0.5f; e += 1; }
    float f  = m - 1.0f;
    float s  = __fdiv_rn(f, 2.0f + f);
    float s2 = s * s;
    float p  = fmaf(s2, 0.11111111f, 0.14285714f);
    p = fmaf(s2, p, 0.2f);
    p = fmaf(s2, p, 0.33333333f);
    float lm = fmaf(2.0f * s, s2 * p, 2.0f * s);
    float r  = fmaf((float)e, 0.693359375f, lm);
    r = fmaf((float)e, -2.12194440e-4f, r);
    return r;
}

// XLA / Eigen fast-tanh (f32, FMA variant) — bit-matches jnp.tanh on GPU.
__device__ __forceinline__ float xla_tanhf(float x) {
    float ax = fabsf(x);
    float xc = fminf(fmaxf(x, -7.99881172180175781f), 7.99881172180175781f);
    float x2 = xc * xc;
    float p = -2.76076847742355e-16f;
    p = fmaf(x2, p,  2.00018790482477e-13f);
    p = fmaf(x2, p, -8.60467152213735e-11f);
    p = fmaf(x2, p,  5.12229709037114e-08f);
    p = fmaf(x2, p,  1.48572235717979e-05f);
    p = fmaf(x2, p,  6.37261928875436e-04f);
    p = fmaf(x2, p,  4.89352455891786e-03f);
    float num = xc * p;
    float q = 1.19825839466702e-06f;
    q = fmaf(x2, q, 1.18534705686654e-04f);
    q = fmaf(x2, q, 2.26843463243900e-03f);
    q = fmaf(x2, q, 4.89352518554385e-03f);
    float r = __fdiv_rn(num, q);
    return (ax < 0.0004f) ? x : r;
}

// phi(x) = -log(tanh(x/2)) with the reference's exact tanh quantization.
__device__ __forceinline__ float phi_f(float x) {
    return -acc_logf(xla_tanhf(0.5f * x));
}

// |sin(argf)| accurate to ~1e-12: dd-pi reduction + odd Taylor to r^15.
__device__ __forceinline__ float abs_sin_acc(float argf) {
    double a = (double)argf;
    double k = rint(a * 0.31830988618379067154);
    double r = fma(-k, 3.141592653589793116, a);
    r = fma(-k, 1.2246467991473531772e-16, r);
    double r2 = r * r;
    double p = -7.6471637318198164759e-13;
    p = fma(r2, p,  1.6059043836821614599e-10);
    p = fma(r2, p, -2.5052108385441718775e-08);
    p = fma(r2, p,  2.7557319223985890653e-06);
    p = fma(r2, p, -1.9841269841269841253e-04);
    p = fma(r2, p,  8.3333333333333332177e-03);
    p = fma(r2, p, -1.6666666666666666574e-01);
    p = fma(r2, p,  1.0);
    return fabsf((float)(r * p));
}

// ---------------- wide scan kernel: H masks + w_vn sign/nz masks --------
__global__ void k_scan(const float* __restrict__ H, const float* __restrict__ w_vn) {
    int t = blockIdx.x * 256 + threadIdx.x;
    const float* base;
    int c;
    bool isH = (t < HW_WORDS);
    if (isH) {
        int m = t / NW; c = t % NW;
        base = H + (size_t)m * TN + c * 32;
    } else {
        int u = t - HW_WORDS;
        int row = u / NW; c = u % NW;
        base = w_vn + (size_t)row * TN + c * 32;
    }
    int nvec = (c == NW - 1) ? 1 : 8;                 // last word: only 4 floats
    unsigned neg = 0, nz = 0;
    for (int v = 0; v < nvec; v++) {
        float4 f = reinterpret_cast<const float4*>(base)[v];
        int k = v * 4;
        neg |= ((f.x < 0.0f) ? 1u : 0u) << k;
        neg |= ((f.y < 0.0f) ? 1u : 0u) << (k + 1);
        neg |= ((f.z < 0.0f) ? 1u : 0u) << (k + 2);
        neg |= ((f.w < 0.0f) ? 1u : 0u) << (k + 3);
        nz  |= ((f.x != 0.0f) ? 1u : 0u) << k;
        nz  |= ((f.y != 0.0f) ? 1u : 0u) << (k + 1);
        nz  |= ((f.z != 0.0f) ? 1u : 0u) << (k + 2);
        nz  |= ((f.w != 0.0f) ? 1u : 0u) << (k + 3);
    }
    if (isH) {
        (&d_hmask[0][0])[t] = nz;
    } else {
        int u = t - HW_WORDS;
        (&d_wneg[0][0][0])[u] = neg;
        (&d_wnz [0][0][0])[u] = nz;
    }
}

// ---------------- persistent kernel: build + iterate + reduce ------------
__global__ void __launch_bounds__(NTHR, 1)
k_iter(const float* __restrict__ ex, const float* __restrict__ ez,
       const float* __restrict__ ep,
       const float* __restrict__ Gx, const float* __restrict__ Gz,
       const float* __restrict__ w_vn,
       const float* __restrict__ w_llr, const float* __restrict__ w_cn,
       float* __restrict__ out)
{
    const int tid  = threadIdx.x;
    const int gtid = blockIdx.x * NTHR + tid;
    const int lane = tid & 31;
    const int gwid = gtid >> 5;

    // ---- P0: row adjacency from masks + C zero + syndromes + col atomics
    for (int m = gwid; m < MOCC; m += NWARPS) {
        int deg = 0;
        for (int c = 0; c < NW; c++) {
            unsigned hm = d_hmask[m][c];              // broadcast 4B load
            if ((hm >> lane) & 1u) {
                int pos = deg + __popc(hm & ((1u << lane) - 1u));
                if (pos < MAXD) d_row_cols[m][pos] = c * 32 + lane;
            }
            deg += __popc(hm);
        }
        if (deg > MAXD) deg = MAXD;
        if (lane == 0) d_row_deg[m] = deg;
        for (int b = 0; b < BB; b++) d_C[b][m][lane] = 0.0f;
        __syncwarp();
        bool act = (lane < deg);
        int col = act ? d_row_cols[m][lane] : 0;
        if (act) {
            int pos = atomicAdd(&d_col_cnt[col], 1);
            if (pos < CMAXD) d_col_edges[col][pos] = m * MAXD + lane;
        }
        for (int b = 0; b < BB; b++) {
            float e = 0.0f;
            if (act) e = (col < NN) ? ex[b * NN + col] : ez[b * NN + (col - NN)];
            unsigned bal = __ballot_sync(0xffffffffu, act && (e != 0.0f));
            if (lane == 0) d_synsign[b][m] = (__popc(bal) & 1) ? -1.0f : 1.0f;
        }
    }
    gbar();

    // ---- P1: wedge gather + column sort/pad/reset
    for (int t = gtid; t < TT * MOCC * MAXD; t += NT) {
        int slot = t & (MAXD - 1);
        int m    = (t >> 5) & (MOCC - 1);
        int it   = t >> 15;
        float w = 0.0f;
        if (slot < d_row_deg[m]) {
            int col = d_row_cols[m][slot];
            w = w_vn[((size_t)it * MOCC + m) * TN + col];
        }
        d_wedge[it][m][slot] = w;
    }
    for (int j = gtid; j < TN; j += NT) {
        int cnt = d_col_cnt[j];
        if (cnt > CMAXD) cnt = CMAXD;
        int e[CMAXD];
        for (int k = 0; k < cnt; k++) e[k] = d_col_edges[j][k];
        for (int i = 1; i < cnt; i++) {               // ascending m order
            int key = e[i], p = i - 1;
            while (p >= 0 && e[p] > key) { e[p + 1] = e[p]; p--; }
            e[p + 1] = key;
        }
        for (int k = 0; k < cnt; k++) d_col_edges[j][k] = e[k];
        for (int k = cnt; k < PADCD; k++) d_col_edges[j][k] = DUMMY_EDGE;
        d_col_deg[j] = cnt;
        d_col_cnt[j] = 0;                             // reset for next replay
    }
    gbar();

    float e0  = ep[0];
    float llr = acc_logf(__fdiv_rn(1.0f - e0, e0));

    for (int it = 0; it < TT; it++) {
        // ---- CN phase (+ loss terms for it-1) ----
        float gconst = llr * w_llr[0];                // used only when it==0
        for (int t = gwid; t < CN_TASKS + LT_TASKS; t += NWARPS) {
            if (t < CN_TASKS) {
                int b = t >> 10, m = t & 1023;
                const unsigned* wneg = d_wneg[it][m];
                const unsigned* wnz  = d_wnz [it][m];
                int cnt = 0;
                if (it == 0) {
                    unsigned GN = (gconst < 0.0f) ? 0xffffffffu : 0u;
                    unsigned GZ = (gconst != 0.0f) ? 0xffffffffu : 0u;
                    for (int c = lane; c < NW; c += 32)
                        cnt += __popc((GN ^ wneg[c]) & GZ & wnz[c]);
                } else {
                    const unsigned* gneg = d_gneg[b];
                    const unsigned* gnz  = d_gnz [b];
                    for (int c = lane; c < NW; c += 32)
                        cnt += __popc((gneg[c] ^ wneg[c]) & gnz[c] & wnz[c]);
                }
                for (int o = 16; o; o >>= 1) cnt += __shfl_xor_sync(0xffffffffu, cnt, o);
                int parity = cnt & 1;

                int deg = d_row_deg[m];
                bool act = (lane < deg);
                float V = 0.0f, phi = 0.0f;
                int corr = 0;
                if (act) {
                    int j = d_row_cols[m][lane];
                    float G = (it == 0) ? gconst : d_Gamma[b][j];
                    float Cold = d_C[b][m][lane];
                    float w = d_wedge[it][m][lane];
                    float x = G - Cold;
                    x = fminf(fmaxf(x, -30.0f), 30.0f);
                    V = x * w;
                    int pneg = (((G < 0.0f) != (w < 0.0f)) && (G != 0.0f) && (w != 0.0f)) ? 1 : 0;
                    int vneg = (V < 0.0f) ? 1 : 0;
                    corr = pneg ^ vneg;
                    if (V != 0.0f) phi = phi_f(fabsf(V));
                }
                unsigned cb = __ballot_sync(0xffffffffu, corr);
                parity ^= (__popc(cb) & 1);

                float A = phi;
                for (int o = 16; o; o >>= 1) A += __shfl_xor_sync(0xffffffffu, A, o);

                if (act) {
                    float P = parity ? -1.0f : 1.0f;
                    float first = (V < 0.0f) ? -P : P;
                    float s2 = A - phi;
                    float second = (s2 != 0.0f) ? phi_f(s2) : 0.0f;
                    d_C[b][m][lane] = ((first * second) * d_synsign[b][m]) * w_cn[it * MOCC + m];
                }
            } else if (it > 0) {
                int idx = t - CN_TASKS;
                int b = idx / (2 * KK), k2 = idx % (2 * KK);
                const float* Grow  = (k2 < KK) ? Gx + (size_t)k2 * NN : Gz + (size_t)(k2 - KK) * NN;
                const float* pmrow = (k2 < KK) ? &d_pm[b][0] : &d_pm[b][NN];
                float s = 0.0f;
                for (int n = lane; n < NN; n += 32) s += pmrow[n] * Grow[n];
                for (int o = 16; o; o >>= 1) s += __shfl_xor_sync(0xffffffffu, s, o);
                if (lane == 0) d_lossterm[b][k2] = abs_sin_acc(1.5707964f * s);
            }
        }
        gbar();

        // ---- VN phase (+ fixed-order loss sum for it-1) ----
        float wl = w_llr[it + 1];
        for (int t = gwid; t < VN_TASKS + BB; t += NWARPS) {
            if (t < VN_TASKS) {
                int b = t / NW, jw = t % NW;
                int j = jw * 32 + lane;
                bool in = (j < TN);
                float g = 0.0f;
                if (in) {
                    const float* Cb = &d_C[b][0][0];
                    float sum = 0.0f;
                    #pragma unroll
                    for (int k = 0; k < PADCD; k++) sum += Cb[d_col_edges[j][k]];
                    int cd = d_col_deg[j];
                    if (cd > PADCD)
                        for (int k = PADCD; k < cd; k++) sum += Cb[d_col_edges[j][k]];
                    g = llr * wl + sum;
                    d_Gamma[b][j] = g;
                    float mask = (j < NN) ? ex[b * NN + j] : ez[b * NN + (j - NN)];
                    float pmv = 0.0f;
                    if (mask == 1.0f) pmv = __fdiv_rn(1.0f, 1.0f + acc_expf(g));
                    d_pm[b][j] = pmv;
                }
                unsigned bneg = __ballot_sync(0xffffffffu, in && (g < 0.0f));
                unsigned bnz  = __ballot_sync(0xffffffffu, in && (g != 0.0f));
                if (lane == 0) { d_gneg[b][jw] = bneg; d_gnz[b][jw] = bnz; }
            } else if (it > 0 && lane == 0) {
                int b = t - VN_TASKS;
                float tsum = 0.0f;
                for (int k = 0; k < 2 * KK; k++) tsum += d_lossterm[b][k];
                d_loss[b][it - 1] = tsum;
            }
        }
        gbar();
    }

    // ---- epilogue: loss terms for it = TT-1 ----
    for (int t = gwid; t < LT_TASKS; t += NWARPS) {
        int b = t / (2 * KK), k2 = t % (2 * KK);
        const float* Grow  = (k2 < KK) ? Gx + (size_t)k2 * NN : Gz + (size_t)(k2 - KK) * NN;
        const float* pmrow = (k2 < KK) ? &d_pm[b][0] : &d_pm[b][NN];
        float s = 0.0f;
        for (int n = lane; n < NN; n += 32) s += pmrow[n] * Grow[n];
        for (int o = 16; o; o >>= 1) s += __shfl_xor_sync(0xffffffffu, s, o);
        if (lane == 0) d_lossterm[b][k2] = abs_sin_acc(1.5707964f * s);
    }
    gbar();

    // ---- final reduction (block 0, warp 0) ----
    if (blockIdx.x == 0 && tid < 32) {
        float per_b = 0.0f;
        if (lane < BB) {
            float v[TT];
            for (int i = 0; i < TT - 1; i++) v[i] = d_loss[lane][i];
            float s5 = 0.0f;
            for (int k = 0; k < 2 * KK; k++) s5 += d_lossterm[lane][k];
            v[TT - 1] = s5;
            float best = v[0]; int bi = 0;
            for (int i = 1; i < TT; i++) if (v[i] < best) { best = v[i]; bi = i; }
            float cs = 0.0f;
            for (int i = 0; i <= bi; i++) cs += v[i];
            per_b = __fdiv_rn(cs, (float)(bi + 1));
        }
        float tot = 0.0f;
        for (int b = 0; b < BB; b++) tot += __shfl_sync(0xffffffffu, per_b, b);
        if (lane == 0) out[0] = tot * 0.125f;
    }
}

// ---------------- launch ----------------
extern "C" void kernel_launch(void* const* d_in, const int* in_sizes, int n_in,
                              void* d_out, int out_size) {
    const float* ex    = (const float*)d_in[0];
    const float* ez    = (const float*)d_in[1];
    const float* ep    = (const float*)d_in[2];
    const float* H     = (const float*)d_in[3];
    const float* Gx    = (const float*)d_in[6];
    const float* Gz    = (const float*)d_in[7];
    const float* w_vn  = (const float*)d_in[8];
    const float* w_llr = (const float*)d_in[9];
    const float* w_cn  = (const float*)d_in[10];
    float* out = (float*)d_out;

    k_scan<<<SCAN_WORDS / 256, 256>>>(H, w_vn);
    k_iter<<<NBLK, NTHR>>>(ex, ez, ep, Gx, Gz, w_vn, w_llr, w_cn, out);
}

// round 11
// speedup vs baseline: 1.4235x; 1.0170x over previous
#include <cuda_runtime.h>
#include <cuda_bf16.h>
#include <cstdint>

#define NN   882
#define TN   1764
#define MOCC 1024
#define BB   8
#define TT   6
#define KK   24
#define MAXD 32
#define CMAXD 24
#define PADCD 16
#define NW   56                      // ceil(1764/32)
#define DUMMY_EDGE (MOCC * MAXD)     // points at always-zero padding row of d_C

#define HW_WORDS  (MOCC * NW)        // 57344
#define WW_WORDS  (TT * MOCC * NW)   // 344064
#define SCAN_WORDS (HW_WORDS + WW_WORDS)             // 401408 = 1568*256
#define GATH_BLOCKS (TT * MOCC * MAXD / 256)         // 768
#define SORT_BLOCKS ((TN + 255) / 256)               // 7

// cluster kernel geometry: 8 clusters (1/batch) x 8 CTAs x 1024 threads
#define CLSZ   8
#define BPTHR  1024
#define NCW    (CLSZ * (BPTHR / 32))  // 256 warps per cluster
#define LT2    (2 * KK)               // 48 per-batch loss-term tasks

// ---------------- device scratch (no allocations allowed) ----------------
__device__ unsigned d_hmask[MOCC][NW];        // H nonzero bitmasks
__device__ int   d_row_deg[MOCC];
__device__ int   d_row_cols[MOCC][MAXD];
__device__ int   d_col_cnt[TN];               // atomic counters (self-resetting)
__device__ int   d_col_deg[TN];
__device__ int   d_col_edges[TN][CMAXD];      // edge idx = m*MAXD + slot (sorted, padded)
__device__ float d_C[BB][MOCC + 1][MAXD];     // c2v messages; row MOCC = permanent zeros
__device__ float d_wedge[TT][MOCC][MAXD];     // pre-gathered w_vn on edges
__device__ float d_Gamma[BB][TN];
__device__ float d_pm[BB][TN];                // masked prob for loss
__device__ float d_synsign[BB][MOCC];         // (1 - 2*syn)
__device__ float d_loss[BB][TT];
__device__ float d_lossterm[BB][2 * KK];
__device__ float d_lossb[BB];                 // per-batch final scalar
__device__ int   g_done;                      // cross-cluster finish counter
__device__ unsigned d_wneg[TT][MOCC][NW];     // sign bitmasks of w_vn[0..5]
__device__ unsigned d_wnz [TT][MOCC][NW];
__device__ unsigned d_gneg[BB][NW];           // sign bitmasks of Gamma
__device__ unsigned d_gnz [BB][NW];

// cluster-wide barrier with global-memory visibility (threadfence's gpu
// scope emits CCTL.IVALL -> no stale L1 across the barrier)
__device__ __forceinline__ void cbar() {
    __threadfence();
    asm volatile("barrier.cluster.arrive.aligned;" ::: "memory");
    asm volatile("barrier.cluster.wait.aligned;" ::: "memory");
}

// ---------------- accurate fp32 math (flag-independent; rn division) ----
__device__ __forceinline__ float acc_expf(float x) {
    if (x < -87.0f) return 0.0f;
    if (x >  88.0f) return __int_as_float(0x7f800000);
    float kf = rintf(x * 1.4426950408889634f);
    float r  = fmaf(-kf, 0.693359375f, x);
    r = fmaf(kf, 2.12194440e-4f, r);
    float p = 1.9841270e-4f;
    p = fmaf(r, p, 1.3888889e-3f);
    p = fmaf(r, p, 8.3333333e-3f);
    p = fmaf(r, p, 4.1666667e-2f);
    p = fmaf(r, p, 1.6666667e-1f);
    p = fmaf(r, p, 0.5f);
    p = fmaf(r, p, 1.0f);
    p = fmaf(r, p, 1.0f);
    int k = (int)kf;
    float sc = __int_as_float((k + 127) << 23);
    return p * sc;
}

// log for t>0; returns EXACT +-0.0f at t==1.0f (load-bearing for phi semantics)
__device__ __forceinline__ float acc_logf(float t) {
    int ix = __float_as_int(t);
    int e  = ((ix >> 23) & 0xff) - 127;
    float m = __int_as_float((ix & 0x007fffff) | 0x3f800000);   // [1,2)
    if (m > 1.4142135f) { m *= 0.5f; e += 1; }
    float f  = m - 1.0f;
    float s  = __fdiv_rn(f, 2.0f + f);
    float s2 = s * s;
    float p  = fmaf(s2, 0.11111111f, 0.14285714f);
    p = fmaf(s2, p, 0.2f);
    p = fmaf(s2, p, 0.33333333f);
    float lm = fmaf(2.0f * s, s2 * p, 2.0f * s);
    float r  = fmaf((float)e, 0.693359375f, lm);
    r = fmaf((float)e, -2.12194440e-4f, r);
    return r;
}

// XLA / Eigen fast-tanh (f32, FMA variant) — bit-matches jnp.tanh on GPU.
__device__ __forceinline__ float xla_tanhf(float x) {
    float ax = fabsf(x);
    float xc = fminf(fmaxf(x, -7.99881172180175781f), 7.99881172180175781f);
    float x2 = xc * xc;
    float p = -2.76076847742355e-16f;
    p = fmaf(x2, p,  2.00018790482477e-13f);
    p = fmaf(x2, p, -8.60467152213735e-11f);
    p = fmaf(x2, p,  5.12229709037114e-08f);
    p = fmaf(x2, p,  1.48572235717979e-05f);
    p = fmaf(x2, p,  6.37261928875436e-04f);
    p = fmaf(x2, p,  4.89352455891786e-03f);
    float num = xc * p;
    float q = 1.19825839466702e-06f;
    q = fmaf(x2, q, 1.18534705686654e-04f);
    q = fmaf(x2, q, 2.26843463243900e-03f);
    q = fmaf(x2, q, 4.89352518554385e-03f);
    float r = __fdiv_rn(num, q);
    return (ax < 0.0004f) ? x : r;
}

// phi(x) = -log(tanh(x/2)) with the reference's exact tanh quantization.
__device__ __forceinline__ float phi_f(float x) {
    return -acc_logf(xla_tanhf(0.5f * x));
}

// |sin(argf)| accurate to ~1e-12: dd-pi reduction + odd Taylor to r^15.
__device__ __forceinline__ float abs_sin_acc(float argf) {
    double a = (double)argf;
    double k = rint(a * 0.31830988618379067154);
    double r = fma(-k, 3.141592653589793116, a);
    r = fma(-k, 1.2246467991473531772e-16, r);
    double r2 = r * r;
    double p = -7.6471637318198164759e-13;
    p = fma(r2, p,  1.6059043836821614599e-10);
    p = fma(r2, p, -2.5052108385441718775e-08);
    p = fma(r2, p,  2.7557319223985890653e-06);
    p = fma(r2, p, -1.9841269841269841253e-04);
    p = fma(r2, p,  8.3333333333333332177e-03);
    p = fma(r2, p, -1.6666666666666666574e-01);
    p = fma(r2, p,  1.0);
    return fabsf((float)(r * p));
}

// ---------------- wide scan kernel: H masks + w_vn sign/nz masks --------
__global__ void k_scan(const float* __restrict__ H, const float* __restrict__ w_vn) {
    int t = blockIdx.x * 256 + threadIdx.x;
    const float* base;
    int c;
    bool isH = (t < HW_WORDS);
    if (isH) {
        int m = t / NW; c = t % NW;
        base = H + (size_t)m * TN + c * 32;
    } else {
        int u = t - HW_WORDS;
        int row = u / NW; c = u % NW;
        base = w_vn + (size_t)row * TN + c * 32;
    }
    int nvec = (c == NW - 1) ? 1 : 8;                 // last word: only 4 floats
    unsigned neg = 0, nz = 0;
    for (int v = 0; v < nvec; v++) {
        float4 f = reinterpret_cast<const float4*>(base)[v];
        int k = v * 4;
        neg |= ((f.x < 0.0f) ? 1u : 0u) << k;
        neg |= ((f.y < 0.0f) ? 1u : 0u) << (k + 1);
        neg |= ((f.z < 0.0f) ? 1u : 0u) << (k + 2);
        neg |= ((f.w < 0.0f) ? 1u : 0u) << (k + 3);
        nz  |= ((f.x != 0.0f) ? 1u : 0u) << k;
        nz  |= ((f.y != 0.0f) ? 1u : 0u) << (k + 1);
        nz  |= ((f.z != 0.0f) ? 1u : 0u) << (k + 2);
        nz  |= ((f.w != 0.0f) ? 1u : 0u) << (k + 3);
    }
    if (isH) {
        (&d_hmask[0][0])[t] = nz;
    } else {
        int u = t - HW_WORDS;
        (&d_wneg[0][0][0])[u] = neg;
        (&d_wnz [0][0][0])[u] = nz;
    }
}

// ---------------- k_rows: adjacency from masks + C zero + syn + col atomics
__global__ void k_rows(const float* __restrict__ ex, const float* __restrict__ ez) {
    int gw = (blockIdx.x * blockDim.x + threadIdx.x) >> 5;
    int lane = threadIdx.x & 31;
    if (gw >= MOCC) return;
    int m = gw, deg = 0;
    for (int c = 0; c < NW; c++) {
        unsigned hm = d_hmask[m][c];
        if ((hm >> lane) & 1u) {
            int pos = deg + __popc(hm & ((1u << lane) - 1u));
            if (pos < MAXD) d_row_cols[m][pos] = c * 32 + lane;
        }
        deg += __popc(hm);
    }
    if (deg > MAXD) deg = MAXD;
    if (lane == 0) d_row_deg[m] = deg;
    for (int b = 0; b < BB; b++) d_C[b][m][lane] = 0.0f;
    __syncwarp();
    bool act = (lane < deg);
    int col = act ? d_row_cols[m][lane] : 0;
    if (act) {
        int pos = atomicAdd(&d_col_cnt[col], 1);
        if (pos < CMAXD) d_col_edges[col][pos] = m * MAXD + lane;
    }
    for (int b = 0; b < BB; b++) {
        float e = 0.0f;
        if (act) e = (col < NN) ? ex[b * NN + col] : ez[b * NN + (col - NN)];
        unsigned bal = __ballot_sync(0xffffffffu, act && (e != 0.0f));
        if (lane == 0) d_synsign[b][m] = (__popc(bal) & 1) ? -1.0f : 1.0f;
    }
}

// ---------------- k_wprep: wedge gather + column sort/pad/reset ----------
__global__ void k_wprep(const float* __restrict__ w_vn) {
    if (blockIdx.x < GATH_BLOCKS) {
        int t = blockIdx.x * 256 + threadIdx.x;
        int slot = t & (MAXD - 1);
        int m    = (t >> 5) & (MOCC - 1);
        int it   = t >> 15;
        float w = 0.0f;
        if (slot < d_row_deg[m]) {
            int col = d_row_cols[m][slot];
            w = w_vn[((size_t)it * MOCC + m) * TN + col];
        }
        d_wedge[it][m][slot] = w;
    } else {
        int j = (blockIdx.x - GATH_BLOCKS) * 256 + threadIdx.x;
        if (j >= TN) return;
        int cnt = d_col_cnt[j];
        if (cnt > CMAXD) cnt = CMAXD;
        int e[CMAXD];
        for (int k = 0; k < cnt; k++) e[k] = d_col_edges[j][k];
        for (int i = 1; i < cnt; i++) {               // ascending m order
            int key = e[i], p = i - 1;
            while (p >= 0 && e[p] > key) { e[p + 1] = e[p]; p--; }
            e[p + 1] = key;
        }
        for (int k = 0; k < cnt; k++) d_col_edges[j][k] = e[k];
        for (int k = cnt; k < PADCD; k++) d_col_edges[j][k] = DUMMY_EDGE;
        d_col_deg[j] = cnt;
        d_col_cnt[j] = 0;                             // reset for next replay
    }
}

// ---------------- k_bp: per-batch clusters, cluster-synced BP iterations
__global__ void __launch_bounds__(BPTHR, 1) __cluster_dims__(CLSZ, 1, 1)
k_bp(const float* __restrict__ ex, const float* __restrict__ ez,
     const float* __restrict__ ep,
     const float* __restrict__ Gx, const float* __restrict__ Gz,
     const float* __restrict__ w_llr, const float* __restrict__ w_cn,
     float* __restrict__ out)
{
    const int tid  = threadIdx.x;
    const int lane = tid & 31;
    const int b    = blockIdx.x / CLSZ;               // batch for this cluster
    const int rank = blockIdx.x % CLSZ;               // cta rank in cluster
    const int cw   = rank * (BPTHR / 32) + (tid >> 5);  // cluster warp id 0..255

    float e0  = ep[0];
    float llr = acc_logf(__fdiv_rn(1.0f - e0, e0));

    for (int it = 0; it < TT; it++) {
        // ---- CN phase for this batch (+ loss terms for it-1) ----
        float gconst = llr * w_llr[0];                // used only when it==0
        for (int t = cw; t < MOCC + LT2; t += NCW) {
            if (t < MOCC) {
                int m = t;
                const unsigned* wneg = d_wneg[it][m];
                const unsigned* wnz  = d_wnz [it][m];
                int cnt = 0;
                if (it == 0) {
                    unsigned GN = (gconst < 0.0f) ? 0xffffffffu : 0u;
                    unsigned GZ = (gconst != 0.0f) ? 0xffffffffu : 0u;
                    for (int c = lane; c < NW; c += 32)
                        cnt += __popc((GN ^ wneg[c]) & GZ & wnz[c]);
                } else {
                    const unsigned* gneg = d_gneg[b];
                    const unsigned* gnz  = d_gnz [b];
                    for (int c = lane; c < NW; c += 32)
                        cnt += __popc((gneg[c] ^ wneg[c]) & gnz[c] & wnz[c]);
                }
                for (int o = 16; o; o >>= 1) cnt += __shfl_xor_sync(0xffffffffu, cnt, o);
                int parity = cnt & 1;

                int deg = d_row_deg[m];
                bool act = (lane < deg);
                float V = 0.0f, phi = 0.0f;
                int corr = 0;
                if (act) {
                    int j = d_row_cols[m][lane];
                    float G = (it == 0) ? gconst : d_Gamma[b][j];
                    float Cold = d_C[b][m][lane];
                    float w = d_wedge[it][m][lane];
                    float x = G - Cold;
                    x = fminf(fmaxf(x, -30.0f), 30.0f);
                    V = x * w;
                    int pneg = (((G < 0.0f) != (w < 0.0f)) && (G != 0.0f) && (w != 0.0f)) ? 1 : 0;
                    int vneg = (V < 0.0f) ? 1 : 0;
                    corr = pneg ^ vneg;
                    if (V != 0.0f) phi = phi_f(fabsf(V));
                }
                unsigned cb = __ballot_sync(0xffffffffu, corr);
                parity ^= (__popc(cb) & 1);

                float A = phi;
                for (int o = 16; o; o >>= 1) A += __shfl_xor_sync(0xffffffffu, A, o);

                if (act) {
                    float P = parity ? -1.0f : 1.0f;
                    float first = (V < 0.0f) ? -P : P;
                    float s2 = A - phi;
                    float second = (s2 != 0.0f) ? phi_f(s2) : 0.0f;
                    d_C[b][m][lane] = ((first * second) * d_synsign[b][m]) * w_cn[it * MOCC + m];
                }
            } else if (it > 0) {
                int k2 = t - MOCC;
                const float* Grow  = (k2 < KK) ? Gx + (size_t)k2 * NN : Gz + (size_t)(k2 - KK) * NN;
                const float* pmrow = (k2 < KK) ? &d_pm[b][0] : &d_pm[b][NN];
                float s = 0.0f;
                for (int n = lane; n < NN; n += 32) s += pmrow[n] * Grow[n];
                for (int o = 16; o; o >>= 1) s += __shfl_xor_sync(0xffffffffu, s, o);
                if (lane == 0) d_lossterm[b][k2] = abs_sin_acc(1.5707964f * s);
            }
        }
        cbar();

        // ---- VN phase for this batch (+ fixed-order loss sum for it-1) ----
        float wl = w_llr[it + 1];
        for (int t = cw; t < NW + 1; t += NCW) {
            if (t < NW) {
                int jw = t;
                int j = jw * 32 + lane;
                bool in = (j < TN);
                float g = 0.0f;
                if (in) {
                    const float* Cb = &d_C[b][0][0];
                    float sum = 0.0f;
                    #pragma unroll
                    for (int k = 0; k < PADCD; k++) sum += Cb[d_col_edges[j][k]];
                    int cd = d_col_deg[j];
                    if (cd > PADCD)
                        for (int k = PADCD; k < cd; k++) sum += Cb[d_col_edges[j][k]];
                    g = llr * wl + sum;
                    d_Gamma[b][j] = g;
                    float mask = (j < NN) ? ex[b * NN + j] : ez[b * NN + (j - NN)];
                    float pmv = 0.0f;
                    if (mask == 1.0f) pmv = __fdiv_rn(1.0f, 1.0f + acc_expf(g));
                    d_pm[b][j] = pmv;
                }
                unsigned bneg = __ballot_sync(0xffffffffu, in && (g < 0.0f));
                unsigned bnz  = __ballot_sync(0xffffffffu, in && (g != 0.0f));
                if (lane == 0) { d_gneg[b][jw] = bneg; d_gnz[b][jw] = bnz; }
            } else if (it > 0 && lane == 0) {
                float tsum = 0.0f;
                for (int k = 0; k < 2 * KK; k++) tsum += d_lossterm[b][k];
                d_loss[b][it - 1] = tsum;
            }
        }
        cbar();
    }

    // ---- epilogue: loss terms for it = TT-1 ----
    for (int t = cw; t < LT2; t += NCW) {
        int k2 = t;
        const float* Grow  = (k2 < KK) ? Gx + (size_t)k2 * NN : Gz + (size_t)(k2 - KK) * NN;
        const float* pmrow = (k2 < KK) ? &d_pm[b][0] : &d_pm[b][NN];
        float s = 0.0f;
        for (int n = lane; n < NN; n += 32) s += pmrow[n] * Grow[n];
        for (int o = 16; o; o >>= 1) s += __shfl_xor_sync(0xffffffffu, s, o);
        if (lane == 0) d_lossterm[b][k2] = abs_sin_acc(1.5707964f * s);
    }
    cbar();

    // ---- per-batch reduction + cross-cluster finish ----
    if (rank == 0 && tid == 0) {
        float v[TT];
        for (int i = 0; i < TT - 1; i++) v[i] = d_loss[b][i];
        float s5 = 0.0f;
        for (int k = 0; k < 2 * KK; k++) s5 += d_lossterm[b][k];
        v[TT - 1] = s5;
        float best = v[0]; int bi = 0;
        for (int i = 1; i < TT; i++) if (v[i] < best) { best = v[i]; bi = i; }
        float cs = 0.0f;
        for (int i = 0; i <= bi; i++) cs += v[i];
        d_lossb[b] = __fdiv_rn(cs, (float)(bi + 1));
        __threadfence();
        int prev = atomicAdd(&g_done, 1);
        if (prev == BB - 1) {                         // last cluster finishes
            __threadfence();
            float tot = 0.0f;
            for (int bb = 0; bb < BB; bb++) tot += d_lossb[bb];
            out[0] = tot * 0.125f;
            g_done = 0;                               // reset for next replay
            __threadfence();
        }
    }
}

// ---------------- launch ----------------
extern "C" void kernel_launch(void* const* d_in, const int* in_sizes, int n_in,
                              void* d_out, int out_size) {
    const float* ex    = (const float*)d_in[0];
    const float* ez    = (const float*)d_in[1];
    const float* ep    = (const float*)d_in[2];
    const float* H     = (const float*)d_in[3];
    const float* Gx    = (const float*)d_in[6];
    const float* Gz    = (const float*)d_in[7];
    const float* w_vn  = (const float*)d_in[8];
    const float* w_llr = (const float*)d_in[9];
    const float* w_cn  = (const float*)d_in[10];
    float* out = (float*)d_out;

    k_scan <<<SCAN_WORDS / 256, 256>>>(H, w_vn);
    k_rows <<<MOCC / 8, 256>>>(ex, ez);
    k_wprep<<<GATH_BLOCKS + SORT_BLOCKS, 256>>>(w_vn);
    k_bp   <<<BB * CLSZ, BPTHR>>>(ex, ez, ep, Gx, Gz, w_llr, w_cn, out);
}

// round 12
// speedup vs baseline: 1.6173x; 1.1361x over previous
#include <cuda_runtime.h>
#include <cuda_bf16.h>
#include <cstdint>

#define NN   882
#define TN   1764
#define MOCC 1024
#define BB   8
#define TT   6
#define KK   24
#define MAXD 32
#define CMAXD 24
#define PADCD 16
#define NW   56                      // ceil(1764/32)
#define DUMMY_EDGE (MOCC * MAXD)     // points at always-zero padding row of d_C

#define HW_WORDS  (MOCC * NW)        // 57344
#define WW_WORDS  (TT * MOCC * NW)   // 344064
#define SCAN_WORDS (HW_WORDS + WW_WORDS)             // 401408 = 1568*256
#define GATH_BLOCKS (TT * MOCC * MAXD / 256)         // 768
#define SORT_BLOCKS ((TN + 255) / 256)               // 7

// cluster kernel geometry: 8 clusters (1/batch) x 8 CTAs x 1024 threads
#define CLSZ   8
#define BPTHR  1024
#define NCW    (CLSZ * (BPTHR / 32))  // 256 warps per cluster
#define CNP    (MOCC / 2)             // 512 packed CN tasks (2 rows each)
#define LT2    (2 * KK)               // 48 per-batch loss-term tasks

// ---------------- device scratch (no allocations allowed) ----------------
__device__ unsigned d_hmask[MOCC][NW];        // H nonzero bitmasks
__device__ int   d_row_deg[MOCC];
__device__ int   d_row_cols[MOCC][MAXD];
__device__ int   d_col_cnt[TN];               // atomic counters (self-resetting)
__device__ int   d_col_deg[TN];
__device__ int   d_col_edges[TN][CMAXD];      // edge idx = m*MAXD + slot (sorted, padded)
__device__ float d_C[BB][MOCC + 1][MAXD];     // c2v messages; row MOCC = permanent zeros
__device__ float d_wedge[TT][MOCC][MAXD];     // pre-gathered w_vn on edges
__device__ float d_Gamma[BB][TN];
__device__ float d_pm[BB][TN];                // masked prob for loss
__device__ float d_synsign[BB][MOCC];         // (1 - 2*syn)
__device__ float d_loss[BB][TT];
__device__ float d_lossterm[BB][2 * KK];
__device__ float d_lossb[BB];                 // per-batch final scalar
__device__ int   g_done;                      // cross-cluster finish counter
__device__ unsigned d_wneg[TT][MOCC][NW];     // sign bitmasks of w_vn[0..5]
__device__ unsigned d_wnz [TT][MOCC][NW];
__device__ unsigned d_gneg[BB][NW];           // sign bitmasks of Gamma
__device__ unsigned d_gnz [BB][NW];

// cluster-wide barrier; threadfence gives release to L2, cluster.sync's
// CCTL.IVALL invalidates L1 so post-barrier loads see fresh data
__device__ __forceinline__ void cbar() {
    __threadfence();
    asm volatile("barrier.cluster.arrive.aligned;" ::: "memory");
    asm volatile("barrier.cluster.wait.aligned;" ::: "memory");
}

// ---------------- accurate fp32 math (flag-independent; rn division) ----
__device__ __forceinline__ float acc_expf(float x) {
    if (x < -87.0f) return 0.0f;
    if (x >  88.0f) return __int_as_float(0x7f800000);
    float kf = rintf(x * 1.4426950408889634f);
    float r  = fmaf(-kf, 0.693359375f, x);
    r = fmaf(kf, 2.12194440e-4f, r);
    float p = 1.9841270e-4f;
    p = fmaf(r, p, 1.3888889e-3f);
    p = fmaf(r, p, 8.3333333e-3f);
    p = fmaf(r, p, 4.1666667e-2f);
    p = fmaf(r, p, 1.6666667e-1f);
    p = fmaf(r, p, 0.5f);
    p = fmaf(r, p, 1.0f);
    p = fmaf(r, p, 1.0f);
    int k = (int)kf;
    float sc = __int_as_float((k + 127) << 23);
    return p * sc;
}

// log for t>0; returns EXACT +-0.0f at t==1.0f (load-bearing for phi semantics)
__device__ __forceinline__ float acc_logf(float t) {
    int ix = __float_as_int(t);
    int e  = ((ix >> 23) & 0xff) - 127;
    float m = __int_as_float((ix & 0x007fffff) | 0x3f800000);   // [1,2)
    if (m > 1.4142135f) { m *= 0.5f; e += 1; }
    float f  = m - 1.0f;
    float s  = __fdiv_rn(f, 2.0f + f);
    float s2 = s * s;
    float p  = fmaf(s2, 0.11111111f, 0.14285714f);
    p = fmaf(s2, p, 0.2f);
    p = fmaf(s2, p, 0.33333333f);
    float lm = fmaf(2.0f * s, s2 * p, 2.0f * s);
    float r  = fmaf((float)e, 0.693359375f, lm);
    r = fmaf((float)e, -2.12194440e-4f, r);
    return r;
}

// XLA / Eigen fast-tanh (f32, FMA variant) — bit-matches jnp.tanh on GPU.
__device__ __forceinline__ float xla_tanhf(float x) {
    float ax = fabsf(x);
    float xc = fminf(fmaxf(x, -7.99881172180175781f), 7.99881172180175781f);
    float x2 = xc * xc;
    float p = -2.76076847742355e-16f;
    p = fmaf(x2, p,  2.00018790482477e-13f);
    p = fmaf(x2, p, -8.60467152213735e-11f);
    p = fmaf(x2, p,  5.12229709037114e-08f);
    p = fmaf(x2, p,  1.48572235717979e-05f);
    p = fmaf(x2, p,  6.37261928875436e-04f);
    p = fmaf(x2, p,  4.89352455891786e-03f);
    float num = xc * p;
    float q = 1.19825839466702e-06f;
    q = fmaf(x2, q, 1.18534705686654e-04f);
    q = fmaf(x2, q, 2.26843463243900e-03f);
    q = fmaf(x2, q, 4.89352518554385e-03f);
    float r = __fdiv_rn(num, q);
    return (ax < 0.0004f) ? x : r;
}

// phi(x) = -log(tanh(x/2)) with the reference's exact tanh quantization.
__device__ __forceinline__ float phi_f(float x) {
    return -acc_logf(xla_tanhf(0.5f * x));
}

// |sin(argf)| accurate to ~1e-12: dd-pi reduction + odd Taylor to r^15.
__device__ __forceinline__ float abs_sin_acc(float argf) {
    double a = (double)argf;
    double k = rint(a * 0.31830988618379067154);
    double r = fma(-k, 3.141592653589793116, a);
    r = fma(-k, 1.2246467991473531772e-16, r);
    double r2 = r * r;
    double p = -7.6471637318198164759e-13;
    p = fma(r2, p,  1.6059043836821614599e-10);
    p = fma(r2, p, -2.5052108385441718775e-08);
    p = fma(r2, p,  2.7557319223985890653e-06);
    p = fma(r2, p, -1.9841269841269841253e-04);
    p = fma(r2, p,  8.3333333333333332177e-03);
    p = fma(r2, p, -1.6666666666666666574e-01);
    p = fma(r2, p,  1.0);
    return fabsf((float)(r * p));
}

// ---------------- wide scan kernel: H masks + w_vn sign/nz masks --------
__global__ void k_scan(const float* __restrict__ H, const float* __restrict__ w_vn) {
    int t = blockIdx.x * 256 + threadIdx.x;
    const float* base;
    int c;
    bool isH = (t < HW_WORDS);
    if (isH) {
        int m = t / NW; c = t % NW;
        base = H + (size_t)m * TN + c * 32;
    } else {
        int u = t - HW_WORDS;
        int row = u / NW; c = u % NW;
        base = w_vn + (size_t)row * TN + c * 32;
    }
    int nvec = (c == NW - 1) ? 1 : 8;                 // last word: only 4 floats
    unsigned neg = 0, nz = 0;
    for (int v = 0; v < nvec; v++) {
        float4 f = reinterpret_cast<const float4*>(base)[v];
        int k = v * 4;
        neg |= ((f.x < 0.0f) ? 1u : 0u) << k;
        neg |= ((f.y < 0.0f) ? 1u : 0u) << (k + 1);
        neg |= ((f.z < 0.0f) ? 1u : 0u) << (k + 2);
        neg |= ((f.w < 0.0f) ? 1u : 0u) << (k + 3);
        nz  |= ((f.x != 0.0f) ? 1u : 0u) << k;
        nz  |= ((f.y != 0.0f) ? 1u : 0u) << (k + 1);
        nz  |= ((f.z != 0.0f) ? 1u : 0u) << (k + 2);
        nz  |= ((f.w != 0.0f) ? 1u : 0u) << (k + 3);
    }
    if (isH) {
        (&d_hmask[0][0])[t] = nz;
    } else {
        int u = t - HW_WORDS;
        (&d_wneg[0][0][0])[u] = neg;
        (&d_wnz [0][0][0])[u] = nz;
    }
}

// ---------------- k_rows: adjacency from masks + C zero + syn + col atomics
__global__ void k_rows(const float* __restrict__ ex, const float* __restrict__ ez) {
    int gw = (blockIdx.x * blockDim.x + threadIdx.x) >> 5;
    int lane = threadIdx.x & 31;
    if (gw >= MOCC) return;
    int m = gw, deg = 0;
    for (int c = 0; c < NW; c++) {
        unsigned hm = d_hmask[m][c];
        if ((hm >> lane) & 1u) {
            int pos = deg + __popc(hm & ((1u << lane) - 1u));
            if (pos < MAXD) d_row_cols[m][pos] = c * 32 + lane;
        }
        deg += __popc(hm);
    }
    if (deg > MAXD) deg = MAXD;
    if (lane == 0) d_row_deg[m] = deg;
    for (int b = 0; b < BB; b++) d_C[b][m][lane] = 0.0f;
    __syncwarp();
    bool act = (lane < deg);
    int col = act ? d_row_cols[m][lane] : 0;
    if (act) {
        int pos = atomicAdd(&d_col_cnt[col], 1);
        if (pos < CMAXD) d_col_edges[col][pos] = m * MAXD + lane;
    }
    for (int b = 0; b < BB; b++) {
        float e = 0.0f;
        if (act) e = (col < NN) ? ex[b * NN + col] : ez[b * NN + (col - NN)];
        unsigned bal = __ballot_sync(0xffffffffu, act && (e != 0.0f));
        if (lane == 0) d_synsign[b][m] = (__popc(bal) & 1) ? -1.0f : 1.0f;
    }
}

// ---------------- k_wprep: wedge gather + column sort/pad/reset ----------
__global__ void k_wprep(const float* __restrict__ w_vn) {
    if (blockIdx.x < GATH_BLOCKS) {
        int t = blockIdx.x * 256 + threadIdx.x;
        int slot = t & (MAXD - 1);
        int m    = (t >> 5) & (MOCC - 1);
        int it   = t >> 15;
        float w = 0.0f;
        if (slot < d_row_deg[m]) {
            int col = d_row_cols[m][slot];
            w = w_vn[((size_t)it * MOCC + m) * TN + col];
        }
        d_wedge[it][m][slot] = w;
    } else {
        int j = (blockIdx.x - GATH_BLOCKS) * 256 + threadIdx.x;
        if (j >= TN) return;
        int cnt = d_col_cnt[j];
        if (cnt > CMAXD) cnt = CMAXD;
        int e[CMAXD];
        for (int k = 0; k < cnt; k++) e[k] = d_col_edges[j][k];
        for (int i = 1; i < cnt; i++) {               // ascending m order
            int key = e[i], p = i - 1;
            while (p >= 0 && e[p] > key) { e[p + 1] = e[p]; p--; }
            e[p + 1] = key;
        }
        for (int k = 0; k < cnt; k++) d_col_edges[j][k] = e[k];
        for (int k = cnt; k < PADCD; k++) d_col_edges[j][k] = DUMMY_EDGE;
        d_col_deg[j] = cnt;
        d_col_cnt[j] = 0;                             // reset for next replay
    }
}

// ---------------- CN row update, full-warp (solo) path -------------------
__device__ __forceinline__ void cn_solo(int b, int m, int it, float gconst,
                                        int lane, const float* __restrict__ w_cn) {
    const unsigned* wneg = d_wneg[it][m];
    const unsigned* wnz  = d_wnz [it][m];
    int cnt = 0;
    if (it == 0) {
        unsigned GN = (gconst < 0.0f) ? 0xffffffffu : 0u;
        unsigned GZ = (gconst != 0.0f) ? 0xffffffffu : 0u;
        for (int c = lane; c < NW; c += 32)
            cnt += __popc((GN ^ wneg[c]) & GZ & wnz[c]);
    } else {
        const unsigned* gneg = d_gneg[b];
        const unsigned* gnz  = d_gnz [b];
        for (int c = lane; c < NW; c += 32)
            cnt += __popc((gneg[c] ^ wneg[c]) & gnz[c] & wnz[c]);
    }
    for (int o = 16; o; o >>= 1) cnt += __shfl_xor_sync(0xffffffffu, cnt, o);
    int parity = cnt & 1;

    int deg = d_row_deg[m];
    bool act = (lane < deg);
    float V = 0.0f, phi = 0.0f;
    int corr = 0;
    if (act) {
        int j = d_row_cols[m][lane];
        float G = (it == 0) ? gconst : d_Gamma[b][j];
        float Cold = d_C[b][m][lane];
        float w = d_wedge[it][m][lane];
        float x = G - Cold;
        x = fminf(fmaxf(x, -30.0f), 30.0f);
        V = x * w;
        int pneg = (((G < 0.0f) != (w < 0.0f)) && (G != 0.0f) && (w != 0.0f)) ? 1 : 0;
        int vneg = (V < 0.0f) ? 1 : 0;
        corr = pneg ^ vneg;
        if (V != 0.0f) phi = phi_f(fabsf(V));
    }
    unsigned cb = __ballot_sync(0xffffffffu, corr);
    parity ^= (__popc(cb) & 1);

    float A = phi;
    for (int o = 16; o; o >>= 1) A += __shfl_xor_sync(0xffffffffu, A, o);

    if (act) {
        float P = parity ? -1.0f : 1.0f;
        float first = (V < 0.0f) ? -P : P;
        float s2 = A - phi;
        float second = (s2 != 0.0f) ? phi_f(s2) : 0.0f;
        d_C[b][m][lane] = ((first * second) * d_synsign[b][m]) * w_cn[it * MOCC + m];
    }
}

// ---------------- k_bp: per-batch clusters, packed CN rows ---------------
__global__ void __launch_bounds__(BPTHR, 1) __cluster_dims__(CLSZ, 1, 1)
k_bp(const float* __restrict__ ex, const float* __restrict__ ez,
     const float* __restrict__ ep,
     const float* __restrict__ Gx, const float* __restrict__ Gz,
     const float* __restrict__ w_llr, const float* __restrict__ w_cn,
     float* __restrict__ out)
{
    const int tid  = threadIdx.x;
    const int lane = tid & 31;
    const int b    = blockIdx.x / CLSZ;               // batch for this cluster
    const int rank = blockIdx.x % CLSZ;               // cta rank in cluster
    const int cw   = rank * (BPTHR / 32) + (tid >> 5);  // cluster warp id 0..255

    float e0  = ep[0];
    float llr = acc_logf(__fdiv_rn(1.0f - e0, e0));

    for (int it = 0; it < TT; it++) {
        // ---- CN phase: packed two-rows-per-warp (+ loss terms for it-1) ----
        float gconst = llr * w_llr[0];                // used only when it==0
        for (int t = cw; t < CNP + LT2; t += NCW) {
            if (t < CNP) {
                int m1 = 2 * t, m2 = 2 * t + 1;
                int deg1 = d_row_deg[m1], deg2 = d_row_deg[m2];
                if (deg1 <= 16 && deg2 <= 16) {
                    // packed: lanes 0-15 -> m1, lanes 16-31 -> m2
                    int half = lane >> 4;
                    int hl   = lane & 15;
                    int m    = half ? m2 : m1;
                    int deg  = half ? deg2 : deg1;
                    const unsigned* wneg = d_wneg[it][m];
                    const unsigned* wnz  = d_wnz [it][m];
                    int cnt = 0;
                    if (it == 0) {
                        unsigned GN = (gconst < 0.0f) ? 0xffffffffu : 0u;
                        unsigned GZ = (gconst != 0.0f) ? 0xffffffffu : 0u;
                        for (int c = hl; c < NW; c += 16)
                            cnt += __popc((GN ^ wneg[c]) & GZ & wnz[c]);
                    } else {
                        const unsigned* gneg = d_gneg[b];
                        const unsigned* gnz  = d_gnz [b];
                        for (int c = hl; c < NW; c += 16)
                            cnt += __popc((gneg[c] ^ wneg[c]) & gnz[c] & wnz[c]);
                    }
                    for (int o = 8; o; o >>= 1) cnt += __shfl_xor_sync(0xffffffffu, cnt, o);
                    int parity = cnt & 1;

                    bool act = (hl < deg);
                    float V = 0.0f, phi = 0.0f;
                    int corr = 0;
                    if (act) {
                        int j = d_row_cols[m][hl];
                        float G = (it == 0) ? gconst : d_Gamma[b][j];
                        float Cold = d_C[b][m][hl];
                        float w = d_wedge[it][m][hl];
                        float x = G - Cold;
                        x = fminf(fmaxf(x, -30.0f), 30.0f);
                        V = x * w;
                        int pneg = (((G < 0.0f) != (w < 0.0f)) && (G != 0.0f) && (w != 0.0f)) ? 1 : 0;
                        int vneg = (V < 0.0f) ? 1 : 0;
                        corr = pneg ^ vneg;
                        if (V != 0.0f) phi = phi_f(fabsf(V));
                    }
                    unsigned cb = __ballot_sync(0xffffffffu, corr);
                    unsigned hmask = half ? (cb >> 16) : (cb & 0xFFFFu);
                    parity ^= (__popc(hmask) & 1);

                    float A = phi;     // half-tree == solo tree for deg<=16 (zeros pad)
                    for (int o = 8; o; o >>= 1) A += __shfl_xor_sync(0xffffffffu, A, o);

                    if (act) {
                        float P = parity ? -1.0f : 1.0f;
                        float first = (V < 0.0f) ? -P : P;
                        float s2 = A - phi;
                        float second = (s2 != 0.0f) ? phi_f(s2) : 0.0f;
                        d_C[b][m][hl] = ((first * second) * d_synsign[b][m]) * w_cn[it * MOCC + m];
                    }
                } else {
                    // rare fallback: full-warp, sequential rows (bit-identical)
                    cn_solo(b, m1, it, gconst, lane, w_cn);
                    cn_solo(b, m2, it, gconst, lane, w_cn);
                }
            } else if (it > 0) {
                int k2 = t - CNP;
                const float* Grow  = (k2 < KK) ? Gx + (size_t)k2 * NN : Gz + (size_t)(k2 - KK) * NN;
                const float* pmrow = (k2 < KK) ? &d_pm[b][0] : &d_pm[b][NN];
                float s = 0.0f;
                for (int n = lane; n < NN; n += 32) s += pmrow[n] * Grow[n];
                for (int o = 16; o; o >>= 1) s += __shfl_xor_sync(0xffffffffu, s, o);
                if (lane == 0) d_lossterm[b][k2] = abs_sin_acc(1.5707964f * s);
            }
        }
        cbar();

        // ---- VN phase for this batch (+ fixed-order loss sum for it-1) ----
        float wl = w_llr[it + 1];
        for (int t = cw; t < NW + 1; t += NCW) {
            if (t < NW) {
                int jw = t;
                int j = jw * 32 + lane;
                bool in = (j < TN);
                float g = 0.0f;
                if (in) {
                    const float* Cb = &d_C[b][0][0];
                    float sum = 0.0f;
                    #pragma unroll
                    for (int k = 0; k < PADCD; k++) sum += Cb[d_col_edges[j][k]];
                    int cd = d_col_deg[j];
                    if (cd > PADCD)
                        for (int k = PADCD; k < cd; k++) sum += Cb[d_col_edges[j][k]];
                    g = llr * wl + sum;
                    d_Gamma[b][j] = g;
                    float mask = (j < NN) ? ex[b * NN + j] : ez[b * NN + (j - NN)];
                    float pmv = 0.0f;
                    if (mask == 1.0f) pmv = __fdiv_rn(1.0f, 1.0f + acc_expf(g));
                    d_pm[b][j] = pmv;
                }
                unsigned bneg = __ballot_sync(0xffffffffu, in && (g < 0.0f));
                unsigned bnz  = __ballot_sync(0xffffffffu, in && (g != 0.0f));
                if (lane == 0) { d_gneg[b][jw] = bneg; d_gnz[b][jw] = bnz; }
            } else if (it > 0 && lane == 0) {
                float tsum = 0.0f;
                for (int k = 0; k < 2 * KK; k++) tsum += d_lossterm[b][k];
                d_loss[b][it - 1] = tsum;
            }
        }
        cbar();
    }

    // ---- epilogue: loss terms for it = TT-1 ----
    for (int t = cw; t < LT2; t += NCW) {
        int k2 = t;
        const float* Grow  = (k2 < KK) ? Gx + (size_t)k2 * NN : Gz + (size_t)(k2 - KK) * NN;
        const float* pmrow = (k2 < KK) ? &d_pm[b][0] : &d_pm[b][NN];
        float s = 0.0f;
        for (int n = lane; n < NN; n += 32) s += pmrow[n] * Grow[n];
        for (int o = 16; o; o >>= 1) s += __shfl_xor_sync(0xffffffffu, s, o);
        if (lane == 0) d_lossterm[b][k2] = abs_sin_acc(1.5707964f * s);
    }
    cbar();

    // ---- per-batch reduction + cross-cluster finish ----
    if (rank == 0 && tid == 0) {
        float v[TT];
        for (int i = 0; i < TT - 1; i++) v[i] = d_loss[b][i];
        float s5 = 0.0f;
        for (int k = 0; k < 2 * KK; k++) s5 += d_lossterm[b][k];
        v[TT - 1] = s5;
        float best = v[0]; int bi = 0;
        for (int i = 1; i < TT; i++) if (v[i] < best) { best = v[i]; bi = i; }
        float cs = 0.0f;
        for (int i = 0; i <= bi; i++) cs += v[i];
        d_lossb[b] = __fdiv_rn(cs, (float)(bi + 1));
        __threadfence();
        int prev = atomicAdd(&g_done, 1);
        if (prev == BB - 1) {                         // last cluster finishes
            __threadfence();
            float tot = 0.0f;
            for (int bb = 0; bb < BB; bb++) tot += d_lossb[bb];
            out[0] = tot * 0.125f;
            g_done = 0;                               // reset for next replay
            __threadfence();
        }
    }
}

// ---------------- launch ----------------
extern "C" void kernel_launch(void* const* d_in, const int* in_sizes, int n_in,
                              void* d_out, int out_size) {
    const float* ex    = (const float*)d_in[0];
    const float* ez    = (const float*)d_in[1];
    const float* ep    = (const float*)d_in[2];
    const float* H     = (const float*)d_in[3];
    const float* Gx    = (const float*)d_in[6];
    const float* Gz    = (const float*)d_in[7];
    const float* w_vn  = (const float*)d_in[8];
    const float* w_llr = (const float*)d_in[9];
    const float* w_cn  = (const float*)d_in[10];
    float* out = (float*)d_out;

    k_scan <<<SCAN_WORDS / 256, 256>>>(H, w_vn);
    k_rows <<<MOCC / 8, 256>>>(ex, ez);
    k_wprep<<<GATH_BLOCKS + SORT_BLOCKS, 256>>>(w_vn);
    k_bp   <<<BB * CLSZ, BPTHR>>>(ex, ez, ep, Gx, Gz, w_llr, w_cn, out);
}

// round 13
// speedup vs baseline: 1.9468x; 1.2037x over previous
#include <cuda_runtime.h>
#include <cuda_bf16.h>
#include <cstdint>

#define NN   882
#define TN   1764
#define MOCC 1024
#define BB   8
#define TT   6
#define KK   24
#define MAXD 32
#define CMAXD 24
#define PADCD 16
#define NW   56                      // ceil(1764/32)
#define DUMMY_EDGE (MOCC * MAXD)     // points at always-zero padding row of d_C

#define HW_WORDS  (MOCC * NW)        // 57344
#define WW_WORDS  (TT * MOCC * NW)   // 344064
#define SCAN_WORDS (HW_WORDS + WW_WORDS)             // 401408 = 1568*256
#define GATH_BLOCKS (TT * MOCC * MAXD / 256)         // 768
#define SORT_BLOCKS ((TN + 255) / 256)               // 7

// cluster kernel geometry: 8 clusters (1/batch) x 8 CTAs x 1024 threads
#define CLSZ   8
#define BPTHR  1024
#define NCW    (CLSZ * (BPTHR / 32))  // 256 warps per cluster
#define CNP    (MOCC / 2)             // 512 packed CN tasks = exactly 2 per warp
#define LT2    (2 * KK)               // 48 per-batch loss-term tasks

// ---------------- device scratch (no allocations allowed) ----------------
__device__ unsigned d_hmask[MOCC][NW];        // H nonzero bitmasks
__device__ int   d_row_deg[MOCC];
__device__ int   d_row_cols[MOCC][MAXD];
__device__ int   d_col_cnt[TN];               // atomic counters (self-resetting)
__device__ int   d_col_deg[TN];
__device__ int   d_col_edges[TN][CMAXD];      // edge idx = m*MAXD + slot (sorted, padded)
__device__ float d_C[BB][MOCC + 1][MAXD];     // c2v messages; row MOCC = permanent zeros
__device__ float d_wedge[TT][MOCC][MAXD];     // pre-gathered w_vn on edges
__device__ float d_Gamma[BB][TN];
__device__ float d_pm2[2][BB][TN];            // double-buffered masked prob
__device__ float d_synsign[BB][MOCC];         // (1 - 2*syn)
__device__ float d_lossterm2[BB][TT][LT2];
__device__ float d_lossb[BB];                 // per-batch final scalar
__device__ int   g_done;                      // cross-cluster finish counter
__device__ unsigned d_wneg[TT][MOCC][NW];     // sign bitmasks of w_vn[0..5]
__device__ unsigned d_wnz [TT][MOCC][NW];
__device__ unsigned d_gneg[BB][NW];           // sign bitmasks of Gamma
__device__ unsigned d_gnz [BB][NW];

// cluster barrier: arrive defaults to .release, wait to .acquire (cluster
// scope, covers global memory among cluster CTAs; acquire flushes stale L1).
__device__ __forceinline__ void cbar() {
    asm volatile("barrier.cluster.arrive.aligned;" ::: "memory");
    asm volatile("barrier.cluster.wait.aligned;" ::: "memory");
}

// ---------------- accurate fp32 math (flag-independent; rn division) ----
__device__ __forceinline__ float acc_expf(float x) {
    if (x < -87.0f) return 0.0f;
    if (x >  88.0f) return __int_as_float(0x7f800000);
    float kf = rintf(x * 1.4426950408889634f);
    float r  = fmaf(-kf, 0.693359375f, x);
    r = fmaf(kf, 2.12194440e-4f, r);
    float p = 1.9841270e-4f;
    p = fmaf(r, p, 1.3888889e-3f);
    p = fmaf(r, p, 8.3333333e-3f);
    p = fmaf(r, p, 4.1666667e-2f);
    p = fmaf(r, p, 1.6666667e-1f);
    p = fmaf(r, p, 0.5f);
    p = fmaf(r, p, 1.0f);
    p = fmaf(r, p, 1.0f);
    int k = (int)kf;
    float sc = __int_as_float((k + 127) << 23);
    return p * sc;
}

// log for t>0; returns EXACT +-0.0f at t==1.0f (load-bearing for phi semantics)
__device__ __forceinline__ float acc_logf(float t) {
    int ix = __float_as_int(t);
    int e  = ((ix >> 23) & 0xff) - 127;
    float m = __int_as_float((ix & 0x007fffff) | 0x3f800000);   // [1,2)
    if (m > 1.4142135f) { m *= 0.5f; e += 1; }
    float f  = m - 1.0f;
    float s  = __fdiv_rn(f, 2.0f + f);
    float s2 = s * s;
    float p  = fmaf(s2, 0.11111111f, 0.14285714f);
    p = fmaf(s2, p, 0.2f);
    p = fmaf(s2, p, 0.33333333f);
    float lm = fmaf(2.0f * s, s2 * p, 2.0f * s);
    float r  = fmaf((float)e, 0.693359375f, lm);
    r = fmaf((float)e, -2.12194440e-4f, r);
    return r;
}

// XLA / Eigen fast-tanh (f32, FMA variant) — bit-matches jnp.tanh on GPU.
__device__ __forceinline__ float xla_tanhf(float x) {
    float ax = fabsf(x);
    float xc = fminf(fmaxf(x, -7.99881172180175781f), 7.99881172180175781f);
    float x2 = xc * xc;
    float p = -2.76076847742355e-16f;
    p = fmaf(x2, p,  2.00018790482477e-13f);
    p = fmaf(x2, p, -8.60467152213735e-11f);
    p = fmaf(x2, p,  5.12229709037114e-08f);
    p = fmaf(x2, p,  1.48572235717979e-05f);
    p = fmaf(x2, p,  6.37261928875436e-04f);
    p = fmaf(x2, p,  4.89352455891786e-03f);
    float num = xc * p;
    float q = 1.19825839466702e-06f;
    q = fmaf(x2, q, 1.18534705686654e-04f);
    q = fmaf(x2, q, 2.26843463243900e-03f);
    q = fmaf(x2, q, 4.89352518554385e-03f);
    float r = __fdiv_rn(num, q);
    return (ax < 0.0004f) ? x : r;
}

// phi(x) = -log(tanh(x/2)) with the reference's exact tanh quantization.
__device__ __forceinline__ float phi_f(float x) {
    return -acc_logf(xla_tanhf(0.5f * x));
}

// |sin(argf)| accurate to ~1e-12: dd-pi reduction + odd Taylor to r^15.
__device__ __forceinline__ float abs_sin_acc(float argf) {
    double a = (double)argf;
    double k = rint(a * 0.31830988618379067154);
    double r = fma(-k, 3.141592653589793116, a);
    r = fma(-k, 1.2246467991473531772e-16, r);
    double r2 = r * r;
    double p = -7.6471637318198164759e-13;
    p = fma(r2, p,  1.6059043836821614599e-10);
    p = fma(r2, p, -2.5052108385441718775e-08);
    p = fma(r2, p,  2.7557319223985890653e-06);
    p = fma(r2, p, -1.9841269841269841253e-04);
    p = fma(r2, p,  8.3333333333333332177e-03);
    p = fma(r2, p, -1.6666666666666666574e-01);
    p = fma(r2, p,  1.0);
    return fabsf((float)(r * p));
}

// ---------------- wide scan kernel: H masks + w_vn sign/nz masks --------
__global__ void k_scan(const float* __restrict__ H, const float* __restrict__ w_vn) {
    int t = blockIdx.x * 256 + threadIdx.x;
    const float* base;
    int c;
    bool isH = (t < HW_WORDS);
    if (isH) {
        int m = t / NW; c = t % NW;
        base = H + (size_t)m * TN + c * 32;
    } else {
        int u = t - HW_WORDS;
        int row = u / NW; c = u % NW;
        base = w_vn + (size_t)row * TN + c * 32;
    }
    int nvec = (c == NW - 1) ? 1 : 8;                 // last word: only 4 floats
    unsigned neg = 0, nz = 0;
    for (int v = 0; v < nvec; v++) {
        float4 f = reinterpret_cast<const float4*>(base)[v];
        int k = v * 4;
        neg |= ((f.x < 0.0f) ? 1u : 0u) << k;
        neg |= ((f.y < 0.0f) ? 1u : 0u) << (k + 1);
        neg |= ((f.z < 0.0f) ? 1u : 0u) << (k + 2);
        neg |= ((f.w < 0.0f) ? 1u : 0u) << (k + 3);
        nz  |= ((f.x != 0.0f) ? 1u : 0u) << k;
        nz  |= ((f.y != 0.0f) ? 1u : 0u) << (k + 1);
        nz  |= ((f.z != 0.0f) ? 1u : 0u) << (k + 2);
        nz  |= ((f.w != 0.0f) ? 1u : 0u) << (k + 3);
    }
    if (isH) {
        (&d_hmask[0][0])[t] = nz;
    } else {
        int u = t - HW_WORDS;
        (&d_wneg[0][0][0])[u] = neg;
        (&d_wnz [0][0][0])[u] = nz;
    }
}

// ---------------- k_rows: adjacency from masks + C zero + syn + col atomics
__global__ void k_rows(const float* __restrict__ ex, const float* __restrict__ ez) {
    int gw = (blockIdx.x * blockDim.x + threadIdx.x) >> 5;
    int lane = threadIdx.x & 31;
    if (gw >= MOCC) return;
    int m = gw, deg = 0;
    for (int c = 0; c < NW; c++) {
        unsigned hm = d_hmask[m][c];
        if ((hm >> lane) & 1u) {
            int pos = deg + __popc(hm & ((1u << lane) - 1u));
            if (pos < MAXD) d_row_cols[m][pos] = c * 32 + lane;
        }
        deg += __popc(hm);
    }
    if (deg > MAXD) deg = MAXD;
    if (lane == 0) d_row_deg[m] = deg;
    for (int b = 0; b < BB; b++) d_C[b][m][lane] = 0.0f;
    __syncwarp();
    bool act = (lane < deg);
    int col = act ? d_row_cols[m][lane] : 0;
    if (act) {
        int pos = atomicAdd(&d_col_cnt[col], 1);
        if (pos < CMAXD) d_col_edges[col][pos] = m * MAXD + lane;
    }
    for (int b = 0; b < BB; b++) {
        float e = 0.0f;
        if (act) e = (col < NN) ? ex[b * NN + col] : ez[b * NN + (col - NN)];
        unsigned bal = __ballot_sync(0xffffffffu, act && (e != 0.0f));
        if (lane == 0) d_synsign[b][m] = (__popc(bal) & 1) ? -1.0f : 1.0f;
    }
}

// ---------------- k_wprep: wedge gather + column sort/pad/reset ----------
__global__ void k_wprep(const float* __restrict__ w_vn) {
    if (blockIdx.x < GATH_BLOCKS) {
        int t = blockIdx.x * 256 + threadIdx.x;
        int slot = t & (MAXD - 1);
        int m    = (t >> 5) & (MOCC - 1);
        int it   = t >> 15;
        float w = 0.0f;
        if (slot < d_row_deg[m]) {
            int col = d_row_cols[m][slot];
            w = w_vn[((size_t)it * MOCC + m) * TN + col];
        }
        d_wedge[it][m][slot] = w;
    } else {
        int j = (blockIdx.x - GATH_BLOCKS) * 256 + threadIdx.x;
        if (j >= TN) return;
        int cnt = d_col_cnt[j];
        if (cnt > CMAXD) cnt = CMAXD;
        int e[CMAXD];
        for (int k = 0; k < cnt; k++) e[k] = d_col_edges[j][k];
        for (int i = 1; i < cnt; i++) {               // ascending m order
            int key = e[i], p = i - 1;
            while (p >= 0 && e[p] > key) { e[p + 1] = e[p]; p--; }
            e[p + 1] = key;
        }
        for (int k = 0; k < cnt; k++) d_col_edges[j][k] = e[k];
        for (int k = cnt; k < PADCD; k++) d_col_edges[j][k] = DUMMY_EDGE;
        d_col_deg[j] = cnt;
        d_col_cnt[j] = 0;                             // reset for next replay
    }
}

// ---------------- CN row update, full-warp fallback (deg>16 rows) --------
__device__ __forceinline__ void cn_solo(int b, int m, int it, float gconst,
                                        int lane, const float* __restrict__ w_cn) {
    const unsigned* wneg = d_wneg[it][m];
    const unsigned* wnz  = d_wnz [it][m];
    int cnt = 0;
    if (it == 0) {
        unsigned GN = (gconst < 0.0f) ? 0xffffffffu : 0u;
        unsigned GZ = (gconst != 0.0f) ? 0xffffffffu : 0u;
        for (int c = lane; c < NW; c += 32)
            cnt += __popc((GN ^ wneg[c]) & GZ & wnz[c]);
    } else {
        const unsigned* gneg = d_gneg[b];
        const unsigned* gnz  = d_gnz [b];
        for (int c = lane; c < NW; c += 32)
            cnt += __popc((gneg[c] ^ wneg[c]) & gnz[c] & wnz[c]);
    }
    for (int o = 16; o; o >>= 1) cnt += __shfl_xor_sync(0xffffffffu, cnt, o);
    int parity = cnt & 1;

    int deg = d_row_deg[m];
    bool act = (lane < deg);
    float V = 0.0f, phi = 0.0f;
    int corr = 0;
    if (act) {
        int j = d_row_cols[m][lane];
        float G = (it == 0) ? gconst : d_Gamma[b][j];
        float Cold = d_C[b][m][lane];
        float w = d_wedge[it][m][lane];
        float x = G - Cold;
        x = fminf(fmaxf(x, -30.0f), 30.0f);
        V = x * w;
        int pneg = (((G < 0.0f) != (w < 0.0f)) && (G != 0.0f) && (w != 0.0f)) ? 1 : 0;
        int vneg = (V < 0.0f) ? 1 : 0;
        corr = pneg ^ vneg;
        if (V != 0.0f) phi = phi_f(fabsf(V));
    }
    unsigned cb = __ballot_sync(0xffffffffu, corr);
    parity ^= (__popc(cb) & 1);

    float A = phi;
    for (int o = 16; o; o >>= 1) A += __shfl_xor_sync(0xffffffffu, A, o);

    if (act) {
        float P = parity ? -1.0f : 1.0f;
        float first = (V < 0.0f) ? -P : P;
        float s2 = A - phi;
        float second = (s2 != 0.0f) ? phi_f(s2) : 0.0f;
        d_C[b][m][lane] = ((first * second) * d_synsign[b][m]) * w_cn[it * MOCC + m];
    }
}

// ---------------- k_bp: per-batch clusters, register-resident state ------
__global__ void __launch_bounds__(BPTHR, 1) __cluster_dims__(CLSZ, 1, 1)
k_bp(const float* __restrict__ ex, const float* __restrict__ ez,
     const float* __restrict__ ep,
     const float* __restrict__ Gx, const float* __restrict__ Gz,
     const float* __restrict__ w_llr, const float* __restrict__ w_cn,
     float* __restrict__ out)
{
    const int tid  = threadIdx.x;
    const int lane = tid & 31;
    const int b    = blockIdx.x / CLSZ;               // batch for this cluster
    const int rank = blockIdx.x % CLSZ;               // cta rank in cluster
    const int cw   = rank * (BPTHR / 32) + (tid >> 5);  // cluster warp id 0..255
    const int half = lane >> 4;
    const int hl   = lane & 15;

    // ---- prologue: cache static per-warp state in registers ----
    // CN tasks s=0,1: t = cw + s*256; rows 2t, 2t+1
    int  cn_m[2], cn_j[2];
    bool cn_act[2], cn_packed[2];
    float cn_syn[2], Creg[2];
    #pragma unroll
    for (int s = 0; s < 2; s++) {
        int t = cw + s * 256;
        int m1 = 2 * t, m2 = 2 * t + 1;
        int deg1 = d_row_deg[m1], deg2 = d_row_deg[m2];
        cn_packed[s] = (deg1 <= 16 && deg2 <= 16);
        int m   = half ? m2 : m1;
        int deg = half ? deg2 : deg1;
        cn_m[s]   = m;
        cn_act[s] = (hl < deg);
        cn_j[s]   = cn_act[s] ? d_row_cols[m][hl] : 0;
        cn_syn[s] = d_synsign[b][m];
        Creg[s]   = 0.0f;
    }
    // VN task: warp cw < 56 handles word-group jw = cw
    int vj = cw * 32 + lane;
    bool vin = (cw < NW) && (vj < TN);
    int  ve[PADCD];
    int  vcd = 0;
    bool vmask = false;
    if (vin) {
        vcd = d_col_deg[vj];
        #pragma unroll
        for (int k = 0; k < PADCD; k++) ve[k] = d_col_edges[vj][k];
        float mk = (vj < NN) ? ex[b * NN + vj] : ez[b * NN + (vj - NN)];
        vmask = (mk == 1.0f);
    } else {
        #pragma unroll
        for (int k = 0; k < PADCD; k++) ve[k] = DUMMY_EDGE;
    }

    float e0  = ep[0];
    float llr = acc_logf(__fdiv_rn(1.0f - e0, e0));
    float gconst = llr * w_llr[0];

    for (int it = 0; it < TT; it++) {
        // ---- CN phase: exactly 2 packed tasks per warp ----
        #pragma unroll
        for (int s = 0; s < 2; s++) {
            int t = cw + s * 256;
            if (cn_packed[s]) {
                int m = cn_m[s];
                // independent loads (overlap the Gamma gather)
                float w   = cn_act[s] ? d_wedge[it][m][hl] : 0.0f;
                float wcn = w_cn[it * MOCC + m];
                const unsigned* wneg = d_wneg[it][m];
                const unsigned* wnz  = d_wnz [it][m];
                int cnt = 0;
                if (it == 0) {
                    unsigned GN = (gconst < 0.0f) ? 0xffffffffu : 0u;
                    unsigned GZ = (gconst != 0.0f) ? 0xffffffffu : 0u;
                    for (int c = hl; c < NW; c += 16)
                        cnt += __popc((GN ^ wneg[c]) & GZ & wnz[c]);
                } else {
                    const unsigned* gneg = d_gneg[b];
                    const unsigned* gnz  = d_gnz [b];
                    for (int c = hl; c < NW; c += 16)
                        cnt += __popc((gneg[c] ^ wneg[c]) & gnz[c] & wnz[c]);
                }
                for (int o = 8; o; o >>= 1) cnt += __shfl_xor_sync(0xffffffffu, cnt, o);
                int parity = cnt & 1;

                float V = 0.0f, phi = 0.0f;
                int corr = 0;
                if (cn_act[s]) {
                    float G = (it == 0) ? gconst : d_Gamma[b][cn_j[s]];
                    float x = G - Creg[s];
                    x = fminf(fmaxf(x, -30.0f), 30.0f);
                    V = x * w;
                    int pneg = (((G < 0.0f) != (w < 0.0f)) && (G != 0.0f) && (w != 0.0f)) ? 1 : 0;
                    int vneg = (V < 0.0f) ? 1 : 0;
                    corr = pneg ^ vneg;
                    if (V != 0.0f) phi = phi_f(fabsf(V));
                }
                unsigned cb = __ballot_sync(0xffffffffu, corr);
                unsigned hmask = half ? (cb >> 16) : (cb & 0xFFFFu);
                parity ^= (__popc(hmask) & 1);

                float A = phi;   // half-tree == solo tree for deg<=16 (zero pad)
                for (int o = 8; o; o >>= 1) A += __shfl_xor_sync(0xffffffffu, A, o);

                if (cn_act[s]) {
                    float P = parity ? -1.0f : 1.0f;
                    float first = (V < 0.0f) ? -P : P;
                    float s2 = A - phi;
                    float second = (s2 != 0.0f) ? phi_f(s2) : 0.0f;
                    float outv = ((first * second) * cn_syn[s]) * wcn;
                    Creg[s] = outv;
                    d_C[b][m][hl] = outv;
                }
            } else {
                cn_solo(b, 2 * t,     it, gconst, lane, w_cn);
                cn_solo(b, 2 * t + 1, it, gconst, lane, w_cn);
            }
        }
        cbar();

        // ---- VN phase (1 task/warp) + loss terms for it-1 ----
        float wl = w_llr[it + 1];
        if (cw < NW) {
            float g = 0.0f;
            if (vin) {
                const float* Cb = &d_C[b][0][0];
                float sum = 0.0f;
                #pragma unroll
                for (int k = 0; k < PADCD; k++) sum += Cb[ve[k]];
                if (vcd > PADCD)
                    for (int k = PADCD; k < vcd; k++) sum += Cb[d_col_edges[vj][k]];
                g = llr * wl + sum;
                d_Gamma[b][vj] = g;
                float pmv = 0.0f;
                if (vmask) pmv = __fdiv_rn(1.0f, 1.0f + acc_expf(g));
                d_pm2[it & 1][b][vj] = pmv;
            }
            unsigned bneg = __ballot_sync(0xffffffffu, vin && (g < 0.0f));
            unsigned bnz  = __ballot_sync(0xffffffffu, vin && (g != 0.0f));
            if (lane == 0) { d_gneg[b][cw] = bneg; d_gnz[b][cw] = bnz; }
        } else if (it > 0 && cw < NW + LT2) {
            int k2 = cw - NW;
            int buf = (it - 1) & 1;
            const float* Grow  = (k2 < KK) ? Gx + (size_t)k2 * NN : Gz + (size_t)(k2 - KK) * NN;
            const float* pmrow = (k2 < KK) ? &d_pm2[buf][b][0] : &d_pm2[buf][b][NN];
            float s = 0.0f;
            for (int n = lane; n < NN; n += 32) s += pmrow[n] * Grow[n];
            for (int o = 16; o; o >>= 1) s += __shfl_xor_sync(0xffffffffu, s, o);
            if (lane == 0) d_lossterm2[b][it - 1][k2] = abs_sin_acc(1.5707964f * s);
        }
        cbar();
    }

    // ---- epilogue: loss terms for it = TT-1 (pm buffer (TT-1)&1) ----
    if (cw < LT2) {
        int k2 = cw;
        int buf = (TT - 1) & 1;
        const float* Grow  = (k2 < KK) ? Gx + (size_t)k2 * NN : Gz + (size_t)(k2 - KK) * NN;
        const float* pmrow = (k2 < KK) ? &d_pm2[buf][b][0] : &d_pm2[buf][b][NN];
        float s = 0.0f;
        for (int n = lane; n < NN; n += 32) s += pmrow[n] * Grow[n];
        for (int o = 16; o; o >>= 1) s += __shfl_xor_sync(0xffffffffu, s, o);
        if (lane == 0) d_lossterm2[b][TT - 1][k2] = abs_sin_acc(1.5707964f * s);
    }
    cbar();

    // ---- per-batch reduction + cross-cluster finish ----
    if (rank == 0 && tid == 0) {
        float v[TT];
        for (int i = 0; i < TT; i++) {
            float tsum = 0.0f;
            for (int k = 0; k < LT2; k++) tsum += d_lossterm2[b][i][k];
            v[i] = tsum;
        }
        float best = v[0]; int bi = 0;
        for (int i = 1; i < TT; i++) if (v[i] < best) { best = v[i]; bi = i; }
        float cs = 0.0f;
        for (int i = 0; i <= bi; i++) cs += v[i];
        d_lossb[b] = __fdiv_rn(cs, (float)(bi + 1));
        __threadfence();
        int prev = atomicAdd(&g_done, 1);
        if (prev == BB - 1) {                         // last cluster finishes
            __threadfence();
            float tot = 0.0f;
            for (int bb = 0; bb < BB; bb++) tot += d_lossb[bb];
            out[0] = tot * 0.125f;
            g_done = 0;                               // reset for next replay
            __threadfence();
        }
    }
}

// ---------------- launch ----------------
extern "C" void kernel_launch(void* const* d_in, const int* in_sizes, int n_in,
                              void* d_out, int out_size) {
    const float* ex    = (const float*)d_in[0];
    const float* ez    = (const float*)d_in[1];
    const float* ep    = (const float*)d_in[2];
    const float* H     = (const float*)d_in[3];
    const float* Gx    = (const float*)d_in[6];
    const float* Gz    = (const float*)d_in[7];
    const float* w_vn  = (const float*)d_in[8];
    const float* w_llr = (const float*)d_in[9];
    const float* w_cn  = (const float*)d_in[10];
    float* out = (float*)d_out;

    k_scan <<<SCAN_WORDS / 256, 256>>>(H, w_vn);
    k_rows <<<MOCC / 8, 256>>>(ex, ez);
    k_wprep<<<GATH_BLOCKS + SORT_BLOCKS, 256>>>(w_vn);
    k_bp   <<<BB * CLSZ, BPTHR>>>(ex, ez, ep, Gx, Gz, w_llr, w_cn, out);
}